// round 14
// baseline (speedup 1.0000x reference)
#include <cuda_runtime.h>
#include <cuda_fp16.h>
#include <math.h>
#include <stdint.h>

#define B_     32
#define NTOK   197
#define DIM_   384
#define HEADS_ 12
#define HD_    32
#define HID_   36
#define P_     38809        // 197*197
#define P4_    38812        // padded plane stride (16B-aligned quads)
#define QPP    9703         // quads per plane  (P4_/4)
#define TOK_   6304         // 32*197
#define QKVN_  1152
#define MLPH_  1536
#define CE_BLOCKS 592
#define WTOT   1769472

// dwexp tile: 32 wide x 24 tall, halo 34x26 = 884 px
#define TW     32
#define TH     24
#define HALOW  34
#define HALOH  26
#define HPX    884
#define HPX4   221

// ------------------------- scratch (static device globals) -------------------
__device__ __align__(128) __half g_hh  [TOK_ * DIM_];
__device__ __align__(128) float  g_qkv [TOK_ * QKVN_];
__device__ __align__(128) float  g_attn[(size_t)B_ * HEADS_ * P4_];
__device__ __align__(128) float  g_adw [(size_t)B_ * HID_   * P4_];
__device__ __align__(128) float  g_apro[(size_t)B_ * HEADS_ * P4_];
__device__ __align__(128) __half g_avh [TOK_ * DIM_];
__device__ __align__(128) float  g_x1  [TOK_ * DIM_];
__device__ __align__(128) __half g_mh  [TOK_ * DIM_];
__device__ __align__(128) __half g_mlph[TOK_ * MLPH_];
__device__ __align__(128) __half g_wh  [WTOT];
__device__ __align__(128) double g_stats[384];
__device__ __align__(128) float2 g_sc  [80];
__device__ __align__(128) float4 g_coef[16];
__device__ __align__(128) float  g_xfall[TOK_ * DIM_];

// ------------------------ prep: zero stats + weight convert ------------------
__global__ void prep_k(const float* __restrict__ qkvw, const float* __restrict__ projw,
                       const float* __restrict__ fc1w, const float* __restrict__ fc2w,
                       __half* __restrict__ wh, double* __restrict__ stats) {
    if (blockIdx.x == 0) {
        stats[threadIdx.x] = 0.0;
        if (threadIdx.x < 128) stats[256 + threadIdx.x] = 0.0;
    }
    int i = blockIdx.x * 256 + threadIdx.x;
    if (i >= WTOT) return;
    float v;
    if      (i < 442368)  v = qkvw[i];
    else if (i < 589824)  v = projw[i - 442368];
    else if (i < 1179648) v = fc1w[i - 589824];
    else                  v = fc2w[i - 1179648];
    wh[i] = __float2half(v);
}

// ------------------------------ LayerNorm (fp16 out) -------------------------
__global__ void ln_kernel(const float* __restrict__ x, const float* __restrict__ g,
                          const float* __restrict__ b, __half* __restrict__ out) {
    int t = blockIdx.x, tid = threadIdx.x;
    const float* xr = x + (size_t)t * DIM_;
    float v0 = 0.5f * xr[tid];
    float v1 = 0.5f * xr[tid + 128];
    float v2 = 0.5f * xr[tid + 256];
    float s  = v0 + v1 + v2;
    float s2 = v0 * v0 + v1 * v1 + v2 * v2;
    for (int o = 16; o; o >>= 1) {
        s  += __shfl_down_sync(0xffffffffu, s,  o);
        s2 += __shfl_down_sync(0xffffffffu, s2, o);
    }
    __shared__ float sh[4][2];
    __shared__ float mv[2];
    if ((tid & 31) == 0) { sh[tid >> 5][0] = s; sh[tid >> 5][1] = s2; }
    __syncthreads();
    if (tid == 0) {
        float S = sh[0][0] + sh[1][0] + sh[2][0] + sh[3][0];
        float S2 = sh[0][1] + sh[1][1] + sh[2][1] + sh[3][1];
        float mean = S / (float)DIM_;
        float var  = S2 / (float)DIM_ - mean * mean;
        mv[0] = mean; mv[1] = rsqrtf(var + 1e-5f);
    }
    __syncthreads();
    float mean = mv[0], inv = mv[1];
    __half* orow = out + (size_t)t * DIM_;
    orow[tid]       = __float2half((v0 - mean) * inv * g[tid]       + b[tid]);
    orow[tid + 128] = __float2half((v1 - mean) * inv * g[tid + 128] + b[tid + 128]);
    orow[tid + 256] = __float2half((v2 - mean) * inv * g[tid + 256] + b[tid + 256]);
}

// ---------- fp16 tensor-core GEMM (m16n8k16, cp.async), 64x128 tile ----------
#define HSTRIDE 72
#define AT64 (64 * HSTRIDE)
#define BT128 (128 * HSTRIDE)

__global__ __launch_bounds__(256) void gemm_h(
        const __half* __restrict__ A, const __half* __restrict__ Bm,
        float* __restrict__ C, int M, int N, int K, int epi,
        const float* __restrict__ bias, const float* __restrict__ resid,
        const float* __restrict__ scale) {
    extern __shared__ __half shm[];
    __half* As = shm;                        // 2 * AT64
    __half* Bs = shm + 2 * AT64;             // 2 * BT128
    unsigned sa = (unsigned)__cvta_generic_to_shared(As);
    unsigned sbB = (unsigned)__cvta_generic_to_shared(Bs);
    int tid = threadIdx.x;
    int warp = tid >> 5, lane = tid & 31;
    int g = lane >> 2, tig = lane & 3;
    int wm = (warp & 1) * 32, wn = (warp >> 1) * 32;
    int m0 = blockIdx.y * 64, n0 = blockIdx.x * 128;

    float acc[2][4][4];
#pragma unroll
    for (int mi = 0; mi < 2; mi++)
#pragma unroll
        for (int nj = 0; nj < 4; nj++)
#pragma unroll
            for (int r = 0; r < 4; r++) acc[mi][nj][r] = 0.f;

    int nch = K >> 6;

#define HSTAGE(K0, BUF) do {                                                  \
        _Pragma("unroll")                                                     \
        for (int i = 0; i < 2; i++) {                                         \
            int idx = tid + i * 256;                                          \
            int r = idx >> 3, seg = idx & 7;                                  \
            int rowA = m0 + r; if (rowA >= M) rowA = M - 1;                   \
            asm volatile("cp.async.cg.shared.global [%0], [%1], 16;"          \
                :: "r"(sa + (unsigned)(((BUF) * AT64 + r * HSTRIDE + seg * 8) * 2)), \
                   "l"(A + (size_t)rowA * K + (K0) + seg * 8) : "memory");    \
        }                                                                     \
        _Pragma("unroll")                                                     \
        for (int i = 0; i < 4; i++) {                                         \
            int idx = tid + i * 256;                                          \
            int r = idx >> 3, seg = idx & 7;                                  \
            asm volatile("cp.async.cg.shared.global [%0], [%1], 16;"          \
                :: "r"(sbB + (unsigned)(((BUF) * BT128 + r * HSTRIDE + seg * 8) * 2)), \
                   "l"(Bm + (size_t)(n0 + r) * K + (K0) + seg * 8) : "memory"); \
        }                                                                     \
        asm volatile("cp.async.commit_group;" ::: "memory");                  \
    } while (0)

    HSTAGE(0, 0);
    HSTAGE(64, 1);
    for (int c = 0; c < nch; c++) {
        if (c + 1 < nch) asm volatile("cp.async.wait_group 1;" ::: "memory");
        else             asm volatile("cp.async.wait_group 0;" ::: "memory");
        __syncthreads();
        const unsigned* Au = (const unsigned*)(As + (c & 1) * AT64);
        const unsigned* Bu = (const unsigned*)(Bs + (c & 1) * BT128);
#pragma unroll
        for (int ks = 0; ks < 4; ks++) {
            unsigned a[2][4], bfr[4][2];
#pragma unroll
            for (int mi = 0; mi < 2; mi++) {
                int rr = wm + mi * 16 + g;
                int base = rr * 36 + ks * 8 + tig;
                a[mi][0] = Au[base];
                a[mi][1] = Au[base + 8 * 36];
                a[mi][2] = Au[base + 4];
                a[mi][3] = Au[base + 8 * 36 + 4];
            }
#pragma unroll
            for (int nj = 0; nj < 4; nj++) {
                int cc = wn + nj * 8 + g;
                int base = cc * 36 + ks * 8 + tig;
                bfr[nj][0] = Bu[base];
                bfr[nj][1] = Bu[base + 4];
            }
#pragma unroll
            for (int mi = 0; mi < 2; mi++)
#pragma unroll
                for (int nj = 0; nj < 4; nj++) {
                    asm volatile(
                        "mma.sync.aligned.m16n8k16.row.col.f32.f16.f16.f32 "
                        "{%0,%1,%2,%3},{%4,%5,%6,%7},{%8,%9},{%0,%1,%2,%3};"
                        : "+f"(acc[mi][nj][0]), "+f"(acc[mi][nj][1]),
                          "+f"(acc[mi][nj][2]), "+f"(acc[mi][nj][3])
                        : "r"(a[mi][0]), "r"(a[mi][1]), "r"(a[mi][2]), "r"(a[mi][3]),
                          "r"(bfr[nj][0]), "r"(bfr[nj][1]));
                }
        }
        __syncthreads();
        if (c + 2 < nch) HSTAGE((c + 2) << 6, c & 1);
    }

#pragma unroll
    for (int mi = 0; mi < 2; mi++) {
#pragma unroll
        for (int half = 0; half < 2; half++) {
            int row = m0 + wm + mi * 16 + g + half * 8;
            if (row >= M) continue;
#pragma unroll
            for (int nj = 0; nj < 4; nj++) {
                int col = n0 + wn + nj * 8 + 2 * tig;
                float v0 = acc[mi][nj][half * 2 + 0];
                float v1 = acc[mi][nj][half * 2 + 1];
                size_t o = (size_t)row * N + col;
                if (epi == 0) {
                    *(float2*)&C[o] = make_float2(v0, v1);
                } else if (epi == 1) {
                    *(float2*)&C[o] = make_float2(resid[o] + 2.f * (v0 + bias[col]),
                                                  resid[o + 1] + 2.f * (v1 + bias[col + 1]));
                } else if (epi == 2) {
                    float u0 = v0 + bias[col], u1 = v1 + bias[col + 1];
                    u0 = 0.5f * u0 * (1.f + erff(u0 * 0.70710678118654752f));
                    u1 = 0.5f * u1 * (1.f + erff(u1 * 0.70710678118654752f));
                    __half2 hv = __floats2half2_rn(u0, u1);
                    *(__half2*)&((__half*)C)[o] = hv;
                } else {
                    float u0 = (v0 + bias[col]) * scale[col];
                    float u1 = (v1 + bias[col + 1]) * scale[col + 1];
                    *(float2*)&C[o] = make_float2(resid[o] + 2.f * u0,
                                                  resid[o + 1] + 2.f * u1);
                }
            }
        }
    }
}

// ------- attention logits + softmax; 4 rows/warp; 2-way n-split; fp32 --------
__global__ __launch_bounds__(256) void attn_softmax_k(const float* __restrict__ qkv,
        float* __restrict__ attn) {
    int bh = blockIdx.x, b = bh / HEADS_, h = bh - b * HEADS_;
    __shared__ float Ks[32 * 227];
    const float* base = qkv + (size_t)b * NTOK * QKVN_ + h * HD_;
    for (int i = threadIdx.x; i < NTOK * 32; i += 256) {
        int m = i >> 5, d = i & 31;
        Ks[d * 227 + m] = base[(size_t)m * QKVN_ + DIM_ + d];
    }
    __syncthreads();
    int lane = threadIdx.x & 31, w = threadIdx.x >> 5;
    float* arow = attn + (size_t)bh * P4_;
    for (int pass = blockIdx.y; pass < 7; pass += 2) {
        int n0 = pass * 32 + w * 4;
        if (n0 >= NTOK) continue;
        float q0 = (n0 + 0 < NTOK) ? base[(size_t)(n0 + 0) * QKVN_ + lane] : 0.f;
        float q1 = (n0 + 1 < NTOK) ? base[(size_t)(n0 + 1) * QKVN_ + lane] : 0.f;
        float q2 = (n0 + 2 < NTOK) ? base[(size_t)(n0 + 2) * QKVN_ + lane] : 0.f;
        float q3 = (n0 + 3 < NTOK) ? base[(size_t)(n0 + 3) * QKVN_ + lane] : 0.f;
        float a[4][7];
#pragma unroll
        for (int r = 0; r < 4; r++)
#pragma unroll
            for (int j = 0; j < 7; j++) a[r][j] = 0.f;
#pragma unroll
        for (int d = 0; d < 32; d++) {
            float qv0 = __shfl_sync(0xffffffffu, q0, d);
            float qv1 = __shfl_sync(0xffffffffu, q1, d);
            float qv2 = __shfl_sync(0xffffffffu, q2, d);
            float qv3 = __shfl_sync(0xffffffffu, q3, d);
            const float* kc = &Ks[d * 227 + lane];
            float kj[7];
#pragma unroll
            for (int j = 0; j < 7; j++) kj[j] = kc[j * 32];
#pragma unroll
            for (int j = 0; j < 7; j++) {
                a[0][j] = fmaf(qv0, kj[j], a[0][j]);
                a[1][j] = fmaf(qv1, kj[j], a[1][j]);
                a[2][j] = fmaf(qv2, kj[j], a[2][j]);
                a[3][j] = fmaf(qv3, kj[j], a[3][j]);
            }
        }
#pragma unroll
        for (int r = 0; r < 4; r++) {
            int n = n0 + r;
            if (n >= NTOK) break;
            float* ar = a[r];
#pragma unroll
            for (int j = 0; j < 7; j++) ar[j] *= 0.17677669529663689f;
            if (lane >= 5) ar[6] = -INFINITY;
            float mx = ar[0];
#pragma unroll
            for (int j = 1; j < 7; j++) mx = fmaxf(mx, ar[j]);
            for (int o = 16; o; o >>= 1) mx = fmaxf(mx, __shfl_xor_sync(0xffffffffu, mx, o));
            float sum = 0.f;
#pragma unroll
            for (int j = 0; j < 7; j++) { ar[j] = __expf(ar[j] - mx); sum += ar[j]; }
            for (int o = 16; o; o >>= 1) sum += __shfl_xor_sync(0xffffffffu, sum, o);
            float inv = 1.f / sum;
#pragma unroll
            for (int j = 0; j < 7; j++) {
                int m = lane + 32 * j;
                if (m < NTOK) arow[(size_t)n * NTOK + m] = ar[j] * inv;
            }
        }
    }
}

// ---------------- Gram matrix of attn (12x12), float4 loads ------------------
__global__ __launch_bounds__(256) void gram_k(const float* __restrict__ attn,
                                              double* __restrict__ G) {
    int b = blockIdx.y;
    const float* ap = attn + (size_t)b * HEADS_ * P4_;
    float acc[78];
#pragma unroll
    for (int t = 0; t < 78; t++) acc[t] = 0.f;
    for (int q = blockIdx.x * 256 + threadIdx.x; q < QPP; q += gridDim.x * 256) {
        float4 a[12];
#pragma unroll
        for (int i = 0; i < 12; i++)
            a[i] = ((const float4*)(ap + (size_t)i * P4_))[q];
        int idx = 0;
#pragma unroll
        for (int i = 0; i < 12; i++)
#pragma unroll
            for (int j = 0; j <= i; j++) {
                acc[idx] = fmaf(a[i].x, a[j].x, acc[idx]);
                acc[idx] = fmaf(a[i].y, a[j].y, acc[idx]);
                acc[idx] = fmaf(a[i].z, a[j].z, acc[idx]);
                acc[idx] = fmaf(a[i].w, a[j].w, acc[idx]);
                idx++;
            }
    }
    __shared__ float red[8][78];
    int lane = threadIdx.x & 31, wp = threadIdx.x >> 5;
#pragma unroll
    for (int t = 0; t < 78; t++) {
        float v = acc[t];
        for (int o = 16; o; o >>= 1) v += __shfl_down_sync(0xffffffffu, v, o);
        if (lane == 0) red[wp][t] = v;
    }
    __syncthreads();
    if (threadIdx.x < 78) {
        float s = 0.f;
#pragma unroll
        for (int i = 0; i < 8; i++) s += red[i][threadIdx.x];
        atomicAdd(&G[threadIdx.x], (double)s);
    }
}

// bn1 from Gram
__global__ void bn_fin1(const double* __restrict__ G, const float* __restrict__ w,
                        const float* __restrict__ g, const float* __restrict__ b,
                        float2* __restrict__ sc) {
    __shared__ float Gs[78];
    if (threadIdx.x < 78) Gs[threadIdx.x] = (float)G[threadIdx.x];
    __syncthreads();
    int c = threadIdx.x;
    if (c >= HID_) return;
    float wr[12]; float rs = 0.f;
#pragma unroll
    for (int i = 0; i < 12; i++) { wr[i] = w[c * 12 + i]; rs += wr[i]; }
    float q = 0.f;
    int idx = 0;
#pragma unroll
    for (int i = 0; i < 12; i++) {
#pragma unroll
        for (int j = 0; j < i; j++) { q += 2.f * wr[i] * wr[j] * Gs[idx]; idx++; }
        q += wr[i] * wr[i] * Gs[idx]; idx++;
    }
    double mean = (double)rs / 197.0;
    double var  = (double)q / 1241888.0 - mean * mean;
    float s = (float)((double)g[c] / sqrt(var + 1e-5));
    sc[c] = make_float2(s, (float)((double)b[c] - mean * (double)s));
}

__global__ void bn_fin(const double* __restrict__ sums, const float* __restrict__ g,
                       const float* __restrict__ b, float2* __restrict__ sc, int C) {
    int c = threadIdx.x;
    if (c >= C) return;
    const double cnt = 1241888.0;
    double mean = sums[c] / cnt;
    double var  = sums[C + c] / cnt - mean * mean;
    float s = (float)((double)g[c] / sqrt(var + 1e-5));
    sc[c] = make_float2(s, (float)((double)b[c] - mean * (double)s));
}

// bn3 + abn analytic finalize
__global__ void bn3abn_fin(const double* __restrict__ S, const double* __restrict__ G,
                           const float* __restrict__ g3, const float* __restrict__ b3,
                           const float* __restrict__ gA, const float* __restrict__ bA,
                           float4* __restrict__ coef) {
    int h = threadIdx.x;
    if (h >= HEADS_) return;
    const double cnt = 1241888.0;
    double S1 = S[h], S2 = S[12 + h], X = S[24 + h];
    double mean3 = S1 / cnt, var3 = S2 / cnt - mean3 * mean3;
    double s3 = (double)g3[h] / sqrt(var3 + 1e-5);
    double sh3 = (double)b3[h] - mean3 * s3;
    double Sa0 = 6304.0;
    double Q = G[h * (h + 1) / 2 + h];
    double St  = s3 * S1 + cnt * sh3 + Sa0;
    double St2 = s3 * s3 * S2 + 2.0 * s3 * sh3 * S1 + cnt * sh3 * sh3
               + 2.0 * s3 * X + 2.0 * sh3 * Sa0 + Q;
    double meanA = St / cnt, varA = St2 / cnt - meanA * meanA;
    double sA = (double)gA[h] / sqrt(varA + 1e-5);
    double shA = (double)bA[h] - meanA * sA;
    coef[h] = make_float4((float)(sA * s3), (float)sA, (float)(sA * sh3 + shA), 0.f);
}

// -------- fused conv_expand + bn1 + relu6 + dw3x3 + bn2-stats (fp32) ---------
__global__ __launch_bounds__(256) void dwexp_k(const float* __restrict__ attn,
        const float* __restrict__ wexp, const float2* __restrict__ sc1,
        const float* __restrict__ dww, float* __restrict__ adw, double* __restrict__ sums) {
    extern __shared__ float sm[];
    float* ain = sm;                 // 12*HPX
    float* et  = sm + 12 * HPX;      // 4*HPX
    float* wE  = et + 4 * HPX;       // 432
    float* wD  = wE + 432;           // 324
    float* sc  = wD + 324;           // 72
    float* sacc = sc + 72;           // 72
    float* msks = sacc + 72;         // HPX
    int tid = threadIdx.x;
    int b = blockIdx.z;
    int y0 = blockIdx.y * TH, x0 = blockIdx.x * TW;
    for (int i = tid; i < 432; i += 256) wE[i] = wexp[i];
    for (int i = tid; i < 324; i += 256) wD[i] = dww[i];
    if (tid < 36) { float2 s = sc1[tid]; sc[2 * tid] = s.x; sc[2 * tid + 1] = s.y; }
    if (tid < 72) sacc[tid] = 0.f;
    const float* ab = attn + (size_t)b * HEADS_ * P4_;
    for (int p = tid; p < HPX; p += 256) {
        int ly = p / HALOW, lx = p - ly * HALOW;
        int gy = y0 + ly - 1, gx = x0 + lx - 1;
        bool in = (gy >= 0 && gy < NTOK && gx >= 0 && gx < NTOK);
        msks[p] = in ? 1.f : 0.f;
        size_t off = (size_t)gy * NTOK + gx;
#pragma unroll
        for (int i = 0; i < 12; i++)
            ain[i * HPX + p] = in ? ab[(size_t)i * P4_ + off] : 0.f;
    }
    __syncthreads();
    int c4 = tid >> 6, t64 = tid & 63, tx = t64 & 31, ty0 = t64 >> 5;
    int lane = tid & 31;
    for (int cg = 0; cg < 9; cg++) {
        for (int p4 = tid; p4 < HPX4; p4 += 256) {
            int p = p4 * 4;
            float4 v[12];
#pragma unroll
            for (int i2 = 0; i2 < 12; i2++)
                v[i2] = *(const float4*)(ain + i2 * HPX + p);
            float4 mk = *(const float4*)(msks + p);
#pragma unroll
            for (int cc = 0; cc < 4; cc++) {
                int c = cg * 4 + cc;
                float4 s = make_float4(0.f, 0.f, 0.f, 0.f);
#pragma unroll
                for (int i2 = 0; i2 < 12; i2++) {
                    float wv = wE[c * 12 + i2];
                    s.x = fmaf(wv, v[i2].x, s.x);
                    s.y = fmaf(wv, v[i2].y, s.y);
                    s.z = fmaf(wv, v[i2].z, s.z);
                    s.w = fmaf(wv, v[i2].w, s.w);
                }
                float a = sc[2 * c], bb = sc[2 * c + 1];
                s.x = fminf(fmaxf(fmaf(a, s.x, bb), 0.f), 6.f) * mk.x;
                s.y = fminf(fmaxf(fmaf(a, s.y, bb), 0.f), 6.f) * mk.y;
                s.z = fminf(fmaxf(fmaf(a, s.z, bb), 0.f), 6.f) * mk.z;
                s.w = fminf(fmaxf(fmaf(a, s.w, bb), 0.f), 6.f) * mk.w;
                *(float4*)(et + cc * HPX + p) = s;
            }
        }
        __syncthreads();
        int c = cg * 4 + c4;
        float w9[9];
#pragma unroll
        for (int k = 0; k < 9; k++) w9[k] = wD[c * 9 + k];
        const float* ep = et + c4 * HPX;
        float* op = adw + ((size_t)b * HID_ + c) * P4_;
        int ybase = ty0 * 12;
        int gx = x0 + tx;
        bool colok = (gx < NTOK);
        float ls = 0.f, ls2 = 0.f;
        float r1 = 0.f, r2 = 0.f;
#pragma unroll
        for (int yy = 0; yy < 14; yy++) {
            const float* rp = ep + (ybase + yy) * HALOW + tx;
            float v0 = rp[0], v1 = rp[1], v2 = rp[2];
            float c0 = fmaf(w9[0], v0, fmaf(w9[1], v1, w9[2] * v2));
            float c1 = fmaf(w9[3], v0, fmaf(w9[4], v1, w9[5] * v2));
            float c2 = fmaf(w9[6], v0, fmaf(w9[7], v1, w9[8] * v2));
            if (yy >= 2) {
                int gy = y0 + ybase + yy - 2;
                float out = r2 + c2;
                if (gy < NTOK && colok) {
                    op[gy * NTOK + gx] = out;
                    ls += out;
                    ls2 = fmaf(out, out, ls2);
                }
            }
            r2 = r1 + c1;
            r1 = c0;
        }
        for (int o = 16; o; o >>= 1) {
            ls  += __shfl_down_sync(0xffffffffu, ls,  o);
            ls2 += __shfl_down_sync(0xffffffffu, ls2, o);
        }
        if (lane == 0) { atomicAdd(&sacc[2 * c], ls); atomicAdd(&sacc[2 * c + 1], ls2); }
        __syncthreads();
    }
    if (tid < 36) {
        atomicAdd(&sums[tid],      (double)sacc[2 * tid]);
        atomicAdd(&sums[36 + tid], (double)sacc[2 * tid + 1]);
    }
}

// ---- conv_pro float4: 4 pixels/thread, bn2+relu6 on inputs + bn3 stats ------
__global__ __launch_bounds__(256) void conv_pro_k(const float* __restrict__ adw,
        const float* __restrict__ a0, const float* __restrict__ w,
        const float2* __restrict__ sc, float* __restrict__ apro, double* __restrict__ sums) {
    __shared__ float ws[HEADS_ * HID_];
    __shared__ float2 scs[HID_];
    int tid = threadIdx.x;
    for (int i = tid; i < HEADS_ * HID_; i += 256) ws[i] = w[i];
    if (tid < HID_) scs[tid] = sc[tid];
    __syncthreads();
    float s1[HEADS_], s2[HEADS_], sx[HEADS_];
#pragma unroll
    for (int o = 0; o < HEADS_; o++) { s1[o] = 0.f; s2[o] = 0.f; sx[o] = 0.f; }
    const int NQ = B_ * QPP;
    for (int q = blockIdx.x * 256 + tid; q < NQ; q += CE_BLOCKS * 256) {
        int b = q / QPP, qi = q - b * QPP;
        const float4* ip = (const float4*)(adw + (size_t)b * HID_ * P4_) + qi;
        float4 acc[HEADS_];
#pragma unroll
        for (int o = 0; o < HEADS_; o++) acc[o] = make_float4(0.f, 0.f, 0.f, 0.f);
#pragma unroll 6
        for (int i = 0; i < HID_; i++) {
            float4 v = ip[(size_t)i * QPP];
            float2 s = scs[i];
            v.x = fminf(fmaxf(fmaf(s.x, v.x, s.y), 0.f), 6.f);
            v.y = fminf(fmaxf(fmaf(s.x, v.y, s.y), 0.f), 6.f);
            v.z = fminf(fmaxf(fmaf(s.x, v.z, s.y), 0.f), 6.f);
            v.w = fminf(fmaxf(fmaf(s.x, v.w, s.y), 0.f), 6.f);
#pragma unroll
            for (int o = 0; o < HEADS_; o++) {
                float wv = ws[o * HID_ + i];
                acc[o].x = fmaf(wv, v.x, acc[o].x);
                acc[o].y = fmaf(wv, v.y, acc[o].y);
                acc[o].z = fmaf(wv, v.z, acc[o].z);
                acc[o].w = fmaf(wv, v.w, acc[o].w);
            }
        }
        int p = 4 * qi;
        float m1 = (p + 1 < P_) ? 1.f : 0.f;
        float m2 = (p + 2 < P_) ? 1.f : 0.f;
        float m3 = (p + 3 < P_) ? 1.f : 0.f;
        const float4* zp = (const float4*)(a0 + (size_t)b * HEADS_ * P4_) + qi;
        float4* op = (float4*)(apro + (size_t)b * HEADS_ * P4_) + qi;
#pragma unroll
        for (int o = 0; o < HEADS_; o++) {
            float4 a = acc[o];
            float4 z = zp[(size_t)o * QPP];
            op[(size_t)o * QPP] = a;
            float ay = a.y * m1, az = a.z * m2, aw = a.w * m3;
            s1[o] += a.x + ay + az + aw;
            s2[o] += a.x * a.x + ay * a.y + az * a.z + aw * a.w;
            sx[o] += a.x * z.x + ay * z.y + az * z.z + aw * z.w;
        }
    }
    int lane = tid & 31, wp = tid >> 5;
    __shared__ float red[8][36];
#pragma unroll
    for (int o = 0; o < HEADS_; o++) {
        float v = s1[o], v2 = s2[o], v3 = sx[o];
        for (int off = 16; off; off >>= 1) {
            v  += __shfl_down_sync(0xffffffffu, v,  off);
            v2 += __shfl_down_sync(0xffffffffu, v2, off);
            v3 += __shfl_down_sync(0xffffffffu, v3, off);
        }
        if (lane == 0) { red[wp][o] = v; red[wp][12 + o] = v2; red[wp][24 + o] = v3; }
    }
    __syncthreads();
    if (tid < 36) {
        float s = 0.f;
#pragma unroll
        for (int i = 0; i < 8; i++) s += red[i][tid];
        atomicAdd(&sums[tid], (double)s);
    }
}

// ---- attn_av: 4 rows/pass share V LDS; attn out fp32 + AV fp16 --------------
__global__ __launch_bounds__(256) void attn_av_k(const float* __restrict__ apro,
        const float* __restrict__ a0, const float* __restrict__ qkv,
        const float4* __restrict__ coef, float* __restrict__ attn_out,
        __half* __restrict__ av) {
    int bh = blockIdx.x, b = bh / HEADS_, h = bh - b * HEADS_;
    __shared__ float Vs[NTOK * 33];
    const float* vb = qkv + (size_t)b * NTOK * QKVN_ + 2 * DIM_ + h * HD_;
    int tid = threadIdx.x;
    for (int i = tid; i < NTOK * 32; i += 256) {
        int m = i >> 5, d = i & 31;
        Vs[m * 33 + d] = vb[(size_t)m * QKVN_ + d];
    }
    float4 cf = coef[h];
    const float* tp = apro + (size_t)bh * P4_;
    const float* zp = a0 + (size_t)bh * P4_;
    float* ao = attn_out ? attn_out + (size_t)bh * P_ : (float*)0;
    __syncthreads();
    int lane = tid & 31, w = tid >> 5;
    for (int r0 = 4 * (w + 8 * blockIdx.y); r0 < NTOK; r0 += 64) {
        int nv = NTOK - r0; if (nv > 4) nv = 4;
        float acc[4] = {0.f, 0.f, 0.f, 0.f};
#pragma unroll
        for (int mb = 0; mb < 192; mb += 32) {
            float tv[4];
#pragma unroll
            for (int r = 0; r < 4; r++) {
                if (r < nv) {
                    tv[r] = fmaf(cf.x, tp[(size_t)(r0 + r) * NTOK + mb + lane],
                                 fmaf(cf.y, zp[(size_t)(r0 + r) * NTOK + mb + lane], cf.z));
                    if (ao) ao[(size_t)(r0 + r) * NTOK + mb + lane] = tv[r];
                } else tv[r] = 0.f;
            }
#pragma unroll
            for (int j = 0; j < 32; j++) {
                float vv = Vs[(mb + j) * 33 + lane];
                acc[0] = fmaf(__shfl_sync(0xffffffffu, tv[0], j), vv, acc[0]);
                acc[1] = fmaf(__shfl_sync(0xffffffffu, tv[1], j), vv, acc[1]);
                acc[2] = fmaf(__shfl_sync(0xffffffffu, tv[2], j), vv, acc[2]);
                acc[3] = fmaf(__shfl_sync(0xffffffffu, tv[3], j), vv, acc[3]);
            }
        }
        {
            float tv[4];
#pragma unroll
            for (int r = 0; r < 4; r++) {
                tv[r] = 0.f;
                if (r < nv && lane < 5) {
                    tv[r] = fmaf(cf.x, tp[(size_t)(r0 + r) * NTOK + 192 + lane],
                                 fmaf(cf.y, zp[(size_t)(r0 + r) * NTOK + 192 + lane], cf.z));
                    if (ao) ao[(size_t)(r0 + r) * NTOK + 192 + lane] = tv[r];
                }
            }
#pragma unroll
            for (int j = 0; j < 5; j++) {
                float vv = Vs[(192 + j) * 33 + lane];
                acc[0] = fmaf(__shfl_sync(0xffffffffu, tv[0], j), vv, acc[0]);
                acc[1] = fmaf(__shfl_sync(0xffffffffu, tv[1], j), vv, acc[1]);
                acc[2] = fmaf(__shfl_sync(0xffffffffu, tv[2], j), vv, acc[2]);
                acc[3] = fmaf(__shfl_sync(0xffffffffu, tv[3], j), vv, acc[3]);
            }
        }
#pragma unroll
        for (int r = 0; r < 4; r++)
            if (r < nv)
                av[((size_t)(b * NTOK + r0 + r)) * DIM_ + h * HD_ + lane] = __float2half(acc[r]);
    }
}

// --------------------------------- launcher ----------------------------------
extern "C" void kernel_launch(void* const* d_in, const int* in_sizes, int n_in,
                              void* d_out, int out_size) {
    const float* x          = (const float*)d_in[0];
    const float* ln1_g      = (const float*)d_in[1];
    const float* ln1_b      = (const float*)d_in[2];
    const float* qkv_w      = (const float*)d_in[3];
    const float* conv_exp_w = (const float*)d_in[4];
    const float* bn1_g      = (const float*)d_in[5];
    const float* bn1_b      = (const float*)d_in[6];
    const float* dw_w       = (const float*)d_in[7];
    const float* bn2_g      = (const float*)d_in[8];
    const float* bn2_b      = (const float*)d_in[9];
    const float* conv_pro_w = (const float*)d_in[10];
    const float* bn3_g      = (const float*)d_in[11];
    const float* bn3_b      = (const float*)d_in[12];
    const float* abn_g      = (const float*)d_in[13];
    const float* abn_b      = (const float*)d_in[14];
    const float* proj_b     = (const float*)d_in[16];
    const float* ln2_g      = (const float*)d_in[17];
    const float* ln2_b      = (const float*)d_in[18];
    const float* fc1_b      = (const float*)d_in[20];
    const float* fc2_b      = (const float*)d_in[22];
    const float* scale_ch   = (const float*)d_in[23];

    void* p;
    cudaGetSymbolAddress(&p, g_hh);    __half* hh    = (__half*)p;
    cudaGetSymbolAddress(&p, g_qkv);   float*  qkvb  = (float*)p;
    cudaGetSymbolAddress(&p, g_attn);  float*  attnb = (float*)p;
    cudaGetSymbolAddress(&p, g_adw);   float*  adwb  = (float*)p;
    cudaGetSymbolAddress(&p, g_apro);  float*  aprob = (float*)p;
    cudaGetSymbolAddress(&p, g_avh);   __half* avh   = (__half*)p;
    cudaGetSymbolAddress(&p, g_x1);    float*  x1b   = (float*)p;
    cudaGetSymbolAddress(&p, g_mh);    __half* mh    = (__half*)p;
    cudaGetSymbolAddress(&p, g_mlph);  __half* mlph  = (__half*)p;
    cudaGetSymbolAddress(&p, g_wh);    __half* wh    = (__half*)p;
    cudaGetSymbolAddress(&p, g_stats); double* stats = (double*)p;
    cudaGetSymbolAddress(&p, g_sc);    float2* scb   = (float2*)p;
    cudaGetSymbolAddress(&p, g_coef);  float4* coef  = (float4*)p;
    cudaGetSymbolAddress(&p, g_xfall); float*  xfall = (float*)p;

    const int XSZ = TOK_ * DIM_;
    const int ASZ = B_ * HEADS_ * P_;
    float* xout; float* attnout;
    if (out_size >= XSZ + ASZ)      { xout = (float*)d_out; attnout = (float*)d_out + XSZ; }
    else if (out_size >= ASZ)       { attnout = (float*)d_out; xout = xfall; }
    else                            { xout = (float*)d_out; attnout = (float*)0; }

    const int GEMM_SMEM = (2 * AT64 + 2 * BT128) * 2;   // 55296 B
    const int DWEXP_SMEM = (12 * HPX + 4 * HPX + 432 + 324 + 72 + 72 + HPX) * 4;
    cudaFuncSetAttribute(gemm_h,  cudaFuncAttributeMaxDynamicSharedMemorySize, GEMM_SMEM);
    cudaFuncSetAttribute(dwexp_k, cudaFuncAttributeMaxDynamicSharedMemorySize, DWEXP_SMEM);

    prep_k<<<WTOT / 256, 256>>>(qkv_w, (const float*)d_in[15],
                                (const float*)d_in[19], (const float*)d_in[21], wh, stats);
    ln_kernel<<<TOK_, 128>>>(x, ln1_g, ln1_b, hh);
    gemm_h<<<dim3(QKVN_ / 128, (TOK_ + 63) / 64), 256, GEMM_SMEM>>>(
        hh, wh, qkvb, TOK_, QKVN_, DIM_, 0, 0, 0, 0);
    attn_softmax_k<<<dim3(B_ * HEADS_, 2), 256>>>(qkvb, attnb);

    gram_k<<<dim3(10, B_), 256>>>(attnb, stats);
    bn_fin1<<<1, 128>>>(stats, conv_exp_w, bn1_g, bn1_b, scb);

    dwexp_k<<<dim3(7, 9, B_), 256, DWEXP_SMEM>>>(attnb, conv_exp_w, scb, dw_w, adwb, stats + 96);
    bn_fin<<<1, 64>>>(stats + 96, bn2_g, bn2_b, scb + 36, HID_);

    conv_pro_k<<<CE_BLOCKS, 256>>>(adwb, attnb, conv_pro_w, scb + 36, aprob, stats + 180);
    bn3abn_fin<<<1, 32>>>(stats + 180, stats, bn3_g, bn3_b, abn_g, abn_b, coef);

    attn_av_k<<<dim3(B_ * HEADS_, 2), 256>>>(aprob, attnb, qkvb, coef, attnout, avh);

    gemm_h<<<dim3(DIM_ / 128, (TOK_ + 63) / 64), 256, GEMM_SMEM>>>(
        avh, wh + 442368, x1b, TOK_, DIM_, DIM_, 1, proj_b, x, 0);
    ln_kernel<<<TOK_, 128>>>(x1b, ln2_g, ln2_b, mh);
    gemm_h<<<dim3(MLPH_ / 128, (TOK_ + 63) / 64), 256, GEMM_SMEM>>>(
        mh, wh + 589824, (float*)mlph, TOK_, MLPH_, DIM_, 2, fc1_b, 0, 0);
    gemm_h<<<dim3(DIM_ / 128, (TOK_ + 63) / 64), 256, GEMM_SMEM>>>(
        mlph, wh + 1179648, xout, TOK_, DIM_, MLPH_, 3, fc2_b, x1b, scale_ch);
}

// round 15
// speedup vs baseline: 1.0415x; 1.0415x over previous
#include <cuda_runtime.h>
#include <cuda_fp16.h>
#include <math.h>
#include <stdint.h>

#define B_     32
#define NTOK   197
#define DIM_   384
#define HEADS_ 12
#define HD_    32
#define HID_   36
#define P_     38809        // 197*197
#define P4_    38812        // padded plane stride (16B-aligned quads)
#define QPP    9703         // quads per plane  (P4_/4)
#define TOK_   6304         // 32*197
#define QKVN_  1152
#define MLPH_  1536
#define CE_BLOCKS 592
#define WTOT   1769472

// dwexp tile: 32 wide x 24 tall, halo 34x26 = 884 px
#define TW     32
#define TH     24
#define HALOW  34
#define HALOH  26
#define HPX    884
#define HPX4   221

// ------------------------- scratch (static device globals) -------------------
__device__ __align__(128) __half g_hh  [TOK_ * DIM_];
__device__ __align__(128) float  g_qkv [TOK_ * QKVN_];
__device__ __align__(128) float  g_attn[(size_t)B_ * HEADS_ * P4_];
__device__ __align__(128) float  g_adw [(size_t)B_ * HID_   * P4_];
__device__ __align__(128) float  g_apro[(size_t)B_ * HEADS_ * P4_];
__device__ __align__(128) __half g_avh [TOK_ * DIM_];
__device__ __align__(128) float  g_x1  [TOK_ * DIM_];
__device__ __align__(128) __half g_mh  [TOK_ * DIM_];
__device__ __align__(128) __half g_mlph[TOK_ * MLPH_];
__device__ __align__(128) __half g_wh  [WTOT];
__device__ __align__(128) double g_stats[384];
__device__ __align__(128) float2 g_sc  [80];
__device__ __align__(128) float4 g_coef[16];
__device__ __align__(128) float  g_xfall[TOK_ * DIM_];

// ------------------------ prep: zero stats + weight convert ------------------
__global__ void prep_k(const float* __restrict__ qkvw, const float* __restrict__ projw,
                       const float* __restrict__ fc1w, const float* __restrict__ fc2w,
                       __half* __restrict__ wh, double* __restrict__ stats) {
    if (blockIdx.x == 0) {
        stats[threadIdx.x] = 0.0;
        if (threadIdx.x < 128) stats[256 + threadIdx.x] = 0.0;
    }
    int i = blockIdx.x * 256 + threadIdx.x;
    if (i >= WTOT) return;
    float v;
    if      (i < 442368)  v = qkvw[i];
    else if (i < 589824)  v = projw[i - 442368];
    else if (i < 1179648) v = fc1w[i - 589824];
    else                  v = fc2w[i - 1179648];
    wh[i] = __float2half(v);
}

// ------------------------------ LayerNorm (fp16 out) -------------------------
__global__ void ln_kernel(const float* __restrict__ x, const float* __restrict__ g,
                          const float* __restrict__ b, __half* __restrict__ out) {
    int t = blockIdx.x, tid = threadIdx.x;
    const float* xr = x + (size_t)t * DIM_;
    float v0 = 0.5f * xr[tid];
    float v1 = 0.5f * xr[tid + 128];
    float v2 = 0.5f * xr[tid + 256];
    float s  = v0 + v1 + v2;
    float s2 = v0 * v0 + v1 * v1 + v2 * v2;
    for (int o = 16; o; o >>= 1) {
        s  += __shfl_down_sync(0xffffffffu, s,  o);
        s2 += __shfl_down_sync(0xffffffffu, s2, o);
    }
    __shared__ float sh[4][2];
    __shared__ float mv[2];
    if ((tid & 31) == 0) { sh[tid >> 5][0] = s; sh[tid >> 5][1] = s2; }
    __syncthreads();
    if (tid == 0) {
        float S = sh[0][0] + sh[1][0] + sh[2][0] + sh[3][0];
        float S2 = sh[0][1] + sh[1][1] + sh[2][1] + sh[3][1];
        float mean = S / (float)DIM_;
        float var  = S2 / (float)DIM_ - mean * mean;
        mv[0] = mean; mv[1] = rsqrtf(var + 1e-5f);
    }
    __syncthreads();
    float mean = mv[0], inv = mv[1];
    __half* orow = out + (size_t)t * DIM_;
    orow[tid]       = __float2half((v0 - mean) * inv * g[tid]       + b[tid]);
    orow[tid + 128] = __float2half((v1 - mean) * inv * g[tid + 128] + b[tid + 128]);
    orow[tid + 256] = __float2half((v2 - mean) * inv * g[tid + 256] + b[tid + 256]);
}

// ------------------- fp16 tensor-core GEMM (m16n8k16, cp.async) --------------
#define HSTRIDE 72
#define ATILE_H (128 * HSTRIDE)

__global__ __launch_bounds__(256) void gemm_h(
        const __half* __restrict__ A, const __half* __restrict__ Bm,
        float* __restrict__ C, int M, int N, int K, int epi,
        const float* __restrict__ bias, const float* __restrict__ resid,
        const float* __restrict__ scale) {
    extern __shared__ __half shm[];
    __half* As = shm;
    __half* Bs = shm + 2 * ATILE_H;
    unsigned sa = (unsigned)__cvta_generic_to_shared(As);
    unsigned sbB = (unsigned)__cvta_generic_to_shared(Bs);
    int tid = threadIdx.x;
    int warp = tid >> 5, lane = tid & 31;
    int g = lane >> 2, tig = lane & 3;
    int wm = (warp & 1) * 64, wn = (warp >> 1) * 32;
    int m0 = blockIdx.y * 128, n0 = blockIdx.x * 128;

    float acc[4][4][4];
#pragma unroll
    for (int mi = 0; mi < 4; mi++)
#pragma unroll
        for (int nj = 0; nj < 4; nj++)
#pragma unroll
            for (int r = 0; r < 4; r++) acc[mi][nj][r] = 0.f;

    int nch = K >> 6;

#define HSTAGE(K0, BUF) do {                                                  \
        _Pragma("unroll")                                                     \
        for (int i = 0; i < 4; i++) {                                         \
            int idx = tid + i * 256;                                          \
            int r = idx >> 3, seg = idx & 7;                                  \
            int rowA = m0 + r; if (rowA >= M) rowA = M - 1;                   \
            asm volatile("cp.async.cg.shared.global [%0], [%1], 16;"          \
                :: "r"(sa + (unsigned)(((BUF) * ATILE_H + r * HSTRIDE + seg * 8) * 2)), \
                   "l"(A + (size_t)rowA * K + (K0) + seg * 8) : "memory");    \
            asm volatile("cp.async.cg.shared.global [%0], [%1], 16;"          \
                :: "r"(sbB + (unsigned)(((BUF) * ATILE_H + r * HSTRIDE + seg * 8) * 2)), \
                   "l"(Bm + (size_t)(n0 + r) * K + (K0) + seg * 8) : "memory"); \
        }                                                                     \
        asm volatile("cp.async.commit_group;" ::: "memory");                  \
    } while (0)

    HSTAGE(0, 0);
    HSTAGE(64, 1);
    for (int c = 0; c < nch; c++) {
        if (c + 1 < nch) asm volatile("cp.async.wait_group 1;" ::: "memory");
        else             asm volatile("cp.async.wait_group 0;" ::: "memory");
        __syncthreads();
        const unsigned* Au = (const unsigned*)(As + (c & 1) * ATILE_H);
        const unsigned* Bu = (const unsigned*)(Bs + (c & 1) * ATILE_H);
#pragma unroll
        for (int ks = 0; ks < 4; ks++) {
            unsigned a[4][4], bfr[4][2];
#pragma unroll
            for (int mi = 0; mi < 4; mi++) {
                int rr = wm + mi * 16 + g;
                int base = rr * 36 + ks * 8 + tig;
                a[mi][0] = Au[base];
                a[mi][1] = Au[base + 8 * 36];
                a[mi][2] = Au[base + 4];
                a[mi][3] = Au[base + 8 * 36 + 4];
            }
#pragma unroll
            for (int nj = 0; nj < 4; nj++) {
                int cc = wn + nj * 8 + g;
                int base = cc * 36 + ks * 8 + tig;
                bfr[nj][0] = Bu[base];
                bfr[nj][1] = Bu[base + 4];
            }
#pragma unroll
            for (int mi = 0; mi < 4; mi++)
#pragma unroll
                for (int nj = 0; nj < 4; nj++) {
                    asm volatile(
                        "mma.sync.aligned.m16n8k16.row.col.f32.f16.f16.f32 "
                        "{%0,%1,%2,%3},{%4,%5,%6,%7},{%8,%9},{%0,%1,%2,%3};"
                        : "+f"(acc[mi][nj][0]), "+f"(acc[mi][nj][1]),
                          "+f"(acc[mi][nj][2]), "+f"(acc[mi][nj][3])
                        : "r"(a[mi][0]), "r"(a[mi][1]), "r"(a[mi][2]), "r"(a[mi][3]),
                          "r"(bfr[nj][0]), "r"(bfr[nj][1]));
                }
        }
        __syncthreads();
        if (c + 2 < nch) HSTAGE((c + 2) << 6, c & 1);
    }

#pragma unroll
    for (int mi = 0; mi < 4; mi++) {
#pragma unroll
        for (int half = 0; half < 2; half++) {
            int row = m0 + wm + mi * 16 + g + half * 8;
            if (row >= M) continue;
#pragma unroll
            for (int nj = 0; nj < 4; nj++) {
                int col = n0 + wn + nj * 8 + 2 * tig;
                float v0 = acc[mi][nj][half * 2 + 0];
                float v1 = acc[mi][nj][half * 2 + 1];
                size_t o = (size_t)row * N + col;
                if (epi == 0) {
                    *(float2*)&C[o] = make_float2(v0, v1);
                } else if (epi == 1) {
                    *(float2*)&C[o] = make_float2(resid[o] + 2.f * (v0 + bias[col]),
                                                  resid[o + 1] + 2.f * (v1 + bias[col + 1]));
                } else if (epi == 2) {
                    float u0 = v0 + bias[col], u1 = v1 + bias[col + 1];
                    u0 = 0.5f * u0 * (1.f + erff(u0 * 0.70710678118654752f));
                    u1 = 0.5f * u1 * (1.f + erff(u1 * 0.70710678118654752f));
                    __half2 hv = __floats2half2_rn(u0, u1);
                    *(__half2*)&((__half*)C)[o] = hv;
                } else {
                    float u0 = (v0 + bias[col]) * scale[col];
                    float u1 = (v1 + bias[col + 1]) * scale[col + 1];
                    *(float2*)&C[o] = make_float2(resid[o] + 2.f * u0,
                                                  resid[o + 1] + 2.f * u1);
                }
            }
        }
    }
}

// ------------- attention logits + softmax; 4 rows/warp; fp32 out -------------
__global__ __launch_bounds__(256) void attn_softmax_k(const float* __restrict__ qkv,
        float* __restrict__ attn) {
    int bh = blockIdx.x, b = bh / HEADS_, h = bh - b * HEADS_;
    __shared__ float Ks[32 * 227];
    const float* base = qkv + (size_t)b * NTOK * QKVN_ + h * HD_;
    for (int i = threadIdx.x; i < NTOK * 32; i += 256) {
        int m = i >> 5, d = i & 31;
        Ks[d * 227 + m] = base[(size_t)m * QKVN_ + DIM_ + d];
    }
    __syncthreads();
    int lane = threadIdx.x & 31, w = threadIdx.x >> 5;
    float* arow = attn + (size_t)bh * P4_;
    for (int pass = 0; pass < 7; pass++) {
        int n0 = pass * 32 + w * 4;
        if (n0 >= NTOK) continue;
        float q0 = (n0 + 0 < NTOK) ? base[(size_t)(n0 + 0) * QKVN_ + lane] : 0.f;
        float q1 = (n0 + 1 < NTOK) ? base[(size_t)(n0 + 1) * QKVN_ + lane] : 0.f;
        float q2 = (n0 + 2 < NTOK) ? base[(size_t)(n0 + 2) * QKVN_ + lane] : 0.f;
        float q3 = (n0 + 3 < NTOK) ? base[(size_t)(n0 + 3) * QKVN_ + lane] : 0.f;
        float a[4][7];
#pragma unroll
        for (int r = 0; r < 4; r++)
#pragma unroll
            for (int j = 0; j < 7; j++) a[r][j] = 0.f;
#pragma unroll
        for (int d = 0; d < 32; d++) {
            float qv0 = __shfl_sync(0xffffffffu, q0, d);
            float qv1 = __shfl_sync(0xffffffffu, q1, d);
            float qv2 = __shfl_sync(0xffffffffu, q2, d);
            float qv3 = __shfl_sync(0xffffffffu, q3, d);
            const float* kc = &Ks[d * 227 + lane];
            float kj[7];
#pragma unroll
            for (int j = 0; j < 7; j++) kj[j] = kc[j * 32];
#pragma unroll
            for (int j = 0; j < 7; j++) {
                a[0][j] = fmaf(qv0, kj[j], a[0][j]);
                a[1][j] = fmaf(qv1, kj[j], a[1][j]);
                a[2][j] = fmaf(qv2, kj[j], a[2][j]);
                a[3][j] = fmaf(qv3, kj[j], a[3][j]);
            }
        }
#pragma unroll
        for (int r = 0; r < 4; r++) {
            int n = n0 + r;
            if (n >= NTOK) break;
            float* ar = a[r];
#pragma unroll
            for (int j = 0; j < 7; j++) ar[j] *= 0.17677669529663689f;
            if (lane >= 5) ar[6] = -INFINITY;
            float mx = ar[0];
#pragma unroll
            for (int j = 1; j < 7; j++) mx = fmaxf(mx, ar[j]);
            for (int o = 16; o; o >>= 1) mx = fmaxf(mx, __shfl_xor_sync(0xffffffffu, mx, o));
            float sum = 0.f;
#pragma unroll
            for (int j = 0; j < 7; j++) { ar[j] = __expf(ar[j] - mx); sum += ar[j]; }
            for (int o = 16; o; o >>= 1) sum += __shfl_xor_sync(0xffffffffu, sum, o);
            float inv = 1.f / sum;
#pragma unroll
            for (int j = 0; j < 7; j++) {
                int m = lane + 32 * j;
                if (m < NTOK) arow[(size_t)n * NTOK + m] = ar[j] * inv;
            }
        }
    }
}

// ---------------- Gram matrix of attn (12x12), float4 loads ------------------
__global__ __launch_bounds__(256) void gram_k(const float* __restrict__ attn,
                                              double* __restrict__ G) {
    int b = blockIdx.y;
    const float* ap = attn + (size_t)b * HEADS_ * P4_;
    float acc[78];
#pragma unroll
    for (int t = 0; t < 78; t++) acc[t] = 0.f;
    for (int q = blockIdx.x * 256 + threadIdx.x; q < QPP; q += gridDim.x * 256) {
        float4 a[12];
#pragma unroll
        for (int i = 0; i < 12; i++)
            a[i] = ((const float4*)(ap + (size_t)i * P4_))[q];
        int idx = 0;
#pragma unroll
        for (int i = 0; i < 12; i++)
#pragma unroll
            for (int j = 0; j <= i; j++) {
                acc[idx] = fmaf(a[i].x, a[j].x, acc[idx]);
                acc[idx] = fmaf(a[i].y, a[j].y, acc[idx]);
                acc[idx] = fmaf(a[i].z, a[j].z, acc[idx]);
                acc[idx] = fmaf(a[i].w, a[j].w, acc[idx]);
                idx++;
            }
    }
    __shared__ float red[8][78];
    int lane = threadIdx.x & 31, wp = threadIdx.x >> 5;
#pragma unroll
    for (int t = 0; t < 78; t++) {
        float v = acc[t];
        for (int o = 16; o; o >>= 1) v += __shfl_down_sync(0xffffffffu, v, o);
        if (lane == 0) red[wp][t] = v;
    }
    __syncthreads();
    if (threadIdx.x < 78) {
        float s = 0.f;
#pragma unroll
        for (int i = 0; i < 8; i++) s += red[i][threadIdx.x];
        atomicAdd(&G[threadIdx.x], (double)s);
    }
}

// bn1 from Gram
__global__ void bn_fin1(const double* __restrict__ G, const float* __restrict__ w,
                        const float* __restrict__ g, const float* __restrict__ b,
                        float2* __restrict__ sc) {
    __shared__ float Gs[78];
    if (threadIdx.x < 78) Gs[threadIdx.x] = (float)G[threadIdx.x];
    __syncthreads();
    int c = threadIdx.x;
    if (c >= HID_) return;
    float wr[12]; float rs = 0.f;
#pragma unroll
    for (int i = 0; i < 12; i++) { wr[i] = w[c * 12 + i]; rs += wr[i]; }
    float q = 0.f;
    int idx = 0;
#pragma unroll
    for (int i = 0; i < 12; i++) {
#pragma unroll
        for (int j = 0; j < i; j++) { q += 2.f * wr[i] * wr[j] * Gs[idx]; idx++; }
        q += wr[i] * wr[i] * Gs[idx]; idx++;
    }
    double mean = (double)rs / 197.0;
    double var  = (double)q / 1241888.0 - mean * mean;
    float s = (float)((double)g[c] / sqrt(var + 1e-5));
    sc[c] = make_float2(s, (float)((double)b[c] - mean * (double)s));
}

__global__ void bn_fin(const double* __restrict__ sums, const float* __restrict__ g,
                       const float* __restrict__ b, float2* __restrict__ sc, int C) {
    int c = threadIdx.x;
    if (c >= C) return;
    const double cnt = 1241888.0;
    double mean = sums[c] / cnt;
    double var  = sums[C + c] / cnt - mean * mean;
    float s = (float)((double)g[c] / sqrt(var + 1e-5));
    sc[c] = make_float2(s, (float)((double)b[c] - mean * (double)s));
}

// bn3 + abn analytic finalize
__global__ void bn3abn_fin(const double* __restrict__ S, const double* __restrict__ G,
                           const float* __restrict__ g3, const float* __restrict__ b3,
                           const float* __restrict__ gA, const float* __restrict__ bA,
                           float4* __restrict__ coef) {
    int h = threadIdx.x;
    if (h >= HEADS_) return;
    const double cnt = 1241888.0;
    double S1 = S[h], S2 = S[12 + h], X = S[24 + h];
    double mean3 = S1 / cnt, var3 = S2 / cnt - mean3 * mean3;
    double s3 = (double)g3[h] / sqrt(var3 + 1e-5);
    double sh3 = (double)b3[h] - mean3 * s3;
    double Sa0 = 6304.0;
    double Q = G[h * (h + 1) / 2 + h];
    double St  = s3 * S1 + cnt * sh3 + Sa0;
    double St2 = s3 * s3 * S2 + 2.0 * s3 * sh3 * S1 + cnt * sh3 * sh3
               + 2.0 * s3 * X + 2.0 * sh3 * Sa0 + Q;
    double meanA = St / cnt, varA = St2 / cnt - meanA * meanA;
    double sA = (double)gA[h] / sqrt(varA + 1e-5);
    double shA = (double)bA[h] - meanA * sA;
    coef[h] = make_float4((float)(sA * s3), (float)sA, (float)(sA * sh3 + shA), 0.f);
}

// -------- fused conv_expand + bn1 + relu6 + dw3x3 + bn2-stats (fp32) ---------
// 32x24 tile. Expand: inputs held in REGISTERS across all 9 channel groups
// (each thread owns <=1 quad since HPX4=221<256). DW: sliding window.
__global__ __launch_bounds__(256) void dwexp_k(const float* __restrict__ attn,
        const float* __restrict__ wexp, const float2* __restrict__ sc1,
        const float* __restrict__ dww, float* __restrict__ adw, double* __restrict__ sums) {
    extern __shared__ float sm[];
    float* ain = sm;                 // 12*HPX
    float* et  = sm + 12 * HPX;      // 4*HPX
    float* wE  = et + 4 * HPX;       // 432
    float* wD  = wE + 432;           // 324
    float* sc  = wD + 324;           // 72
    float* sacc = sc + 72;           // 72
    float* msks = sacc + 72;         // HPX
    int tid = threadIdx.x;
    int b = blockIdx.z;
    int y0 = blockIdx.y * TH, x0 = blockIdx.x * TW;
    for (int i = tid; i < 432; i += 256) wE[i] = wexp[i];
    for (int i = tid; i < 324; i += 256) wD[i] = dww[i];
    if (tid < 36) { float2 s = sc1[tid]; sc[2 * tid] = s.x; sc[2 * tid + 1] = s.y; }
    if (tid < 72) sacc[tid] = 0.f;
    const float* ab = attn + (size_t)b * HEADS_ * P4_;
    for (int p = tid; p < HPX; p += 256) {
        int ly = p / HALOW, lx = p - ly * HALOW;
        int gy = y0 + ly - 1, gx = x0 + lx - 1;
        bool in = (gy >= 0 && gy < NTOK && gx >= 0 && gx < NTOK);
        msks[p] = in ? 1.f : 0.f;
        size_t off = (size_t)gy * NTOK + gx;
#pragma unroll
        for (int i = 0; i < 12; i++)
            ain[i * HPX + p] = in ? ab[(size_t)i * P4_ + off] : 0.f;
    }
    __syncthreads();
    // ---- hoist this thread's quad of inputs + mask into registers ----
    bool haveq = (tid < HPX4);
    int myp = tid * 4;
    float4 vreg[12];
    float4 mreg;
    if (haveq) {
#pragma unroll
        for (int i2 = 0; i2 < 12; i2++)
            vreg[i2] = *(const float4*)(ain + i2 * HPX + myp);
        mreg = *(const float4*)(msks + myp);
    } else {
#pragma unroll
        for (int i2 = 0; i2 < 12; i2++) vreg[i2] = make_float4(0.f, 0.f, 0.f, 0.f);
        mreg = make_float4(0.f, 0.f, 0.f, 0.f);
    }
    int c4 = tid >> 6, t64 = tid & 63, tx = t64 & 31, ty0 = t64 >> 5;
    int lane = tid & 31;
    for (int cg = 0; cg < 9; cg++) {
        // ---- expand 4 channels from registers ----
        if (haveq) {
#pragma unroll
            for (int cc = 0; cc < 4; cc++) {
                int c = cg * 4 + cc;
                float4 s = make_float4(0.f, 0.f, 0.f, 0.f);
#pragma unroll
                for (int i2 = 0; i2 < 12; i2++) {
                    float wv = wE[c * 12 + i2];
                    s.x = fmaf(wv, vreg[i2].x, s.x);
                    s.y = fmaf(wv, vreg[i2].y, s.y);
                    s.z = fmaf(wv, vreg[i2].z, s.z);
                    s.w = fmaf(wv, vreg[i2].w, s.w);
                }
                float a = sc[2 * c], bb = sc[2 * c + 1];
                s.x = fminf(fmaxf(fmaf(a, s.x, bb), 0.f), 6.f) * mreg.x;
                s.y = fminf(fmaxf(fmaf(a, s.y, bb), 0.f), 6.f) * mreg.y;
                s.z = fminf(fmaxf(fmaf(a, s.z, bb), 0.f), 6.f) * mreg.z;
                s.w = fminf(fmaxf(fmaf(a, s.w, bb), 0.f), 6.f) * mreg.w;
                *(float4*)(et + cc * HPX + myp) = s;
            }
        }
        __syncthreads();
        // ---- dw 3x3, channel c = cg*4+c4, sliding window over 14 rows ----
        int c = cg * 4 + c4;
        float w9[9];
#pragma unroll
        for (int k = 0; k < 9; k++) w9[k] = wD[c * 9 + k];
        const float* ep = et + c4 * HPX;
        float* op = adw + ((size_t)b * HID_ + c) * P4_;
        int ybase = ty0 * 12;
        int gx = x0 + tx;
        bool colok = (gx < NTOK);
        float ls = 0.f, ls2 = 0.f;
        float r1 = 0.f, r2 = 0.f;
#pragma unroll
        for (int yy = 0; yy < 14; yy++) {
            const float* rp = ep + (ybase + yy) * HALOW + tx;
            float v0 = rp[0], v1 = rp[1], v2 = rp[2];
            float c0 = fmaf(w9[0], v0, fmaf(w9[1], v1, w9[2] * v2));
            float c1 = fmaf(w9[3], v0, fmaf(w9[4], v1, w9[5] * v2));
            float c2 = fmaf(w9[6], v0, fmaf(w9[7], v1, w9[8] * v2));
            if (yy >= 2) {
                int gy = y0 + ybase + yy - 2;
                float out = r2 + c2;
                if (gy < NTOK && colok) {
                    op[gy * NTOK + gx] = out;
                    ls += out;
                    ls2 = fmaf(out, out, ls2);
                }
            }
            r2 = r1 + c1;
            r1 = c0;
        }
        for (int o = 16; o; o >>= 1) {
            ls  += __shfl_down_sync(0xffffffffu, ls,  o);
            ls2 += __shfl_down_sync(0xffffffffu, ls2, o);
        }
        if (lane == 0) { atomicAdd(&sacc[2 * c], ls); atomicAdd(&sacc[2 * c + 1], ls2); }
        __syncthreads();
    }
    if (tid < 36) {
        atomicAdd(&sums[tid],      (double)sacc[2 * tid]);
        atomicAdd(&sums[36 + tid], (double)sacc[2 * tid + 1]);
    }
}

// ---- conv_pro float4: 4 pixels/thread, bn2+relu6 on inputs + bn3 stats ------
__global__ __launch_bounds__(256) void conv_pro_k(const float* __restrict__ adw,
        const float* __restrict__ a0, const float* __restrict__ w,
        const float2* __restrict__ sc, float* __restrict__ apro, double* __restrict__ sums) {
    __shared__ float ws[HEADS_ * HID_];
    __shared__ float2 scs[HID_];
    int tid = threadIdx.x;
    for (int i = tid; i < HEADS_ * HID_; i += 256) ws[i] = w[i];
    if (tid < HID_) scs[tid] = sc[tid];
    __syncthreads();
    float s1[HEADS_], s2[HEADS_], sx[HEADS_];
#pragma unroll
    for (int o = 0; o < HEADS_; o++) { s1[o] = 0.f; s2[o] = 0.f; sx[o] = 0.f; }
    const int NQ = B_ * QPP;
    for (int q = blockIdx.x * 256 + tid; q < NQ; q += CE_BLOCKS * 256) {
        int b = q / QPP, qi = q - b * QPP;
        const float4* ip = (const float4*)(adw + (size_t)b * HID_ * P4_) + qi;
        float4 acc[HEADS_];
#pragma unroll
        for (int o = 0; o < HEADS_; o++) acc[o] = make_float4(0.f, 0.f, 0.f, 0.f);
#pragma unroll 6
        for (int i = 0; i < HID_; i++) {
            float4 v = ip[(size_t)i * QPP];
            float2 s = scs[i];
            v.x = fminf(fmaxf(fmaf(s.x, v.x, s.y), 0.f), 6.f);
            v.y = fminf(fmaxf(fmaf(s.x, v.y, s.y), 0.f), 6.f);
            v.z = fminf(fmaxf(fmaf(s.x, v.z, s.y), 0.f), 6.f);
            v.w = fminf(fmaxf(fmaf(s.x, v.w, s.y), 0.f), 6.f);
#pragma unroll
            for (int o = 0; o < HEADS_; o++) {
                float wv = ws[o * HID_ + i];
                acc[o].x = fmaf(wv, v.x, acc[o].x);
                acc[o].y = fmaf(wv, v.y, acc[o].y);
                acc[o].z = fmaf(wv, v.z, acc[o].z);
                acc[o].w = fmaf(wv, v.w, acc[o].w);
            }
        }
        int p = 4 * qi;
        float m1 = (p + 1 < P_) ? 1.f : 0.f;
        float m2 = (p + 2 < P_) ? 1.f : 0.f;
        float m3 = (p + 3 < P_) ? 1.f : 0.f;
        const float4* zp = (const float4*)(a0 + (size_t)b * HEADS_ * P4_) + qi;
        float4* op = (float4*)(apro + (size_t)b * HEADS_ * P4_) + qi;
#pragma unroll
        for (int o = 0; o < HEADS_; o++) {
            float4 a = acc[o];
            float4 z = zp[(size_t)o * QPP];
            op[(size_t)o * QPP] = a;
            float ay = a.y * m1, az = a.z * m2, aw = a.w * m3;
            s1[o] += a.x + ay + az + aw;
            s2[o] += a.x * a.x + ay * a.y + az * a.z + aw * a.w;
            sx[o] += a.x * z.x + ay * z.y + az * z.z + aw * z.w;
        }
    }
    int lane = tid & 31, wp = tid >> 5;
    __shared__ float red[8][36];
#pragma unroll
    for (int o = 0; o < HEADS_; o++) {
        float v = s1[o], v2 = s2[o], v3 = sx[o];
        for (int off = 16; off; off >>= 1) {
            v  += __shfl_down_sync(0xffffffffu, v,  off);
            v2 += __shfl_down_sync(0xffffffffu, v2, off);
            v3 += __shfl_down_sync(0xffffffffu, v3, off);
        }
        if (lane == 0) { red[wp][o] = v; red[wp][12 + o] = v2; red[wp][24 + o] = v3; }
    }
    __syncthreads();
    if (tid < 36) {
        float s = 0.f;
#pragma unroll
        for (int i = 0; i < 8; i++) s += red[i][tid];
        atomicAdd(&sums[tid], (double)s);
    }
}

// ---- attn_av: 4 rows/pass share V LDS; attn out fp32 + AV fp16 --------------
__global__ __launch_bounds__(256) void attn_av_k(const float* __restrict__ apro,
        const float* __restrict__ a0, const float* __restrict__ qkv,
        const float4* __restrict__ coef, float* __restrict__ attn_out,
        __half* __restrict__ av) {
    int bh = blockIdx.x, b = bh / HEADS_, h = bh - b * HEADS_;
    __shared__ float Vs[NTOK * 33];
    const float* vb = qkv + (size_t)b * NTOK * QKVN_ + 2 * DIM_ + h * HD_;
    int tid = threadIdx.x;
    for (int i = tid; i < NTOK * 32; i += 256) {
        int m = i >> 5, d = i & 31;
        Vs[m * 33 + d] = vb[(size_t)m * QKVN_ + d];
    }
    float4 cf = coef[h];
    const float* tp = apro + (size_t)bh * P4_;
    const float* zp = a0 + (size_t)bh * P4_;
    float* ao = attn_out ? attn_out + (size_t)bh * P_ : (float*)0;
    __syncthreads();
    int lane = tid & 31, w = tid >> 5;
    for (int r0 = 4 * (w + 8 * blockIdx.y); r0 < NTOK; r0 += 64) {
        int nv = NTOK - r0; if (nv > 4) nv = 4;
        float acc[4] = {0.f, 0.f, 0.f, 0.f};
#pragma unroll
        for (int mb = 0; mb < 192; mb += 32) {
            float tv[4];
#pragma unroll
            for (int r = 0; r < 4; r++) {
                if (r < nv) {
                    tv[r] = fmaf(cf.x, tp[(size_t)(r0 + r) * NTOK + mb + lane],
                                 fmaf(cf.y, zp[(size_t)(r0 + r) * NTOK + mb + lane], cf.z));
                    if (ao) ao[(size_t)(r0 + r) * NTOK + mb + lane] = tv[r];
                } else tv[r] = 0.f;
            }
#pragma unroll
            for (int j = 0; j < 32; j++) {
                float vv = Vs[(mb + j) * 33 + lane];
                acc[0] = fmaf(__shfl_sync(0xffffffffu, tv[0], j), vv, acc[0]);
                acc[1] = fmaf(__shfl_sync(0xffffffffu, tv[1], j), vv, acc[1]);
                acc[2] = fmaf(__shfl_sync(0xffffffffu, tv[2], j), vv, acc[2]);
                acc[3] = fmaf(__shfl_sync(0xffffffffu, tv[3], j), vv, acc[3]);
            }
        }
        {
            float tv[4];
#pragma unroll
            for (int r = 0; r < 4; r++) {
                tv[r] = 0.f;
                if (r < nv && lane < 5) {
                    tv[r] = fmaf(cf.x, tp[(size_t)(r0 + r) * NTOK + 192 + lane],
                                 fmaf(cf.y, zp[(size_t)(r0 + r) * NTOK + 192 + lane], cf.z));
                    if (ao) ao[(size_t)(r0 + r) * NTOK + 192 + lane] = tv[r];
                }
            }
#pragma unroll
            for (int j = 0; j < 5; j++) {
                float vv = Vs[(192 + j) * 33 + lane];
                acc[0] = fmaf(__shfl_sync(0xffffffffu, tv[0], j), vv, acc[0]);
                acc[1] = fmaf(__shfl_sync(0xffffffffu, tv[1], j), vv, acc[1]);
                acc[2] = fmaf(__shfl_sync(0xffffffffu, tv[2], j), vv, acc[2]);
                acc[3] = fmaf(__shfl_sync(0xffffffffu, tv[3], j), vv, acc[3]);
            }
        }
#pragma unroll
        for (int r = 0; r < 4; r++)
            if (r < nv)
                av[((size_t)(b * NTOK + r0 + r)) * DIM_ + h * HD_ + lane] = __float2half(acc[r]);
    }
}

// --------------------------------- launcher ----------------------------------
extern "C" void kernel_launch(void* const* d_in, const int* in_sizes, int n_in,
                              void* d_out, int out_size) {
    const float* x          = (const float*)d_in[0];
    const float* ln1_g      = (const float*)d_in[1];
    const float* ln1_b      = (const float*)d_in[2];
    const float* qkv_w      = (const float*)d_in[3];
    const float* conv_exp_w = (const float*)d_in[4];
    const float* bn1_g      = (const float*)d_in[5];
    const float* bn1_b      = (const float*)d_in[6];
    const float* dw_w       = (const float*)d_in[7];
    const float* bn2_g      = (const float*)d_in[8];
    const float* bn2_b      = (const float*)d_in[9];
    const float* conv_pro_w = (const float*)d_in[10];
    const float* bn3_g      = (const float*)d_in[11];
    const float* bn3_b      = (const float*)d_in[12];
    const float* abn_g      = (const float*)d_in[13];
    const float* abn_b      = (const float*)d_in[14];
    const float* proj_b     = (const float*)d_in[16];
    const float* ln2_g      = (const float*)d_in[17];
    const float* ln2_b      = (const float*)d_in[18];
    const float* fc1_b      = (const float*)d_in[20];
    const float* fc2_b      = (const float*)d_in[22];
    const float* scale_ch   = (const float*)d_in[23];

    void* p;
    cudaGetSymbolAddress(&p, g_hh);    __half* hh    = (__half*)p;
    cudaGetSymbolAddress(&p, g_qkv);   float*  qkvb  = (float*)p;
    cudaGetSymbolAddress(&p, g_attn);  float*  attnb = (float*)p;
    cudaGetSymbolAddress(&p, g_adw);   float*  adwb  = (float*)p;
    cudaGetSymbolAddress(&p, g_apro);  float*  aprob = (float*)p;
    cudaGetSymbolAddress(&p, g_avh);   __half* avh   = (__half*)p;
    cudaGetSymbolAddress(&p, g_x1);    float*  x1b   = (float*)p;
    cudaGetSymbolAddress(&p, g_mh);    __half* mh    = (__half*)p;
    cudaGetSymbolAddress(&p, g_mlph);  __half* mlph  = (__half*)p;
    cudaGetSymbolAddress(&p, g_wh);    __half* wh    = (__half*)p;
    cudaGetSymbolAddress(&p, g_stats); double* stats = (double*)p;
    cudaGetSymbolAddress(&p, g_sc);    float2* scb   = (float2*)p;
    cudaGetSymbolAddress(&p, g_coef);  float4* coef  = (float4*)p;
    cudaGetSymbolAddress(&p, g_xfall); float*  xfall = (float*)p;

    const int XSZ = TOK_ * DIM_;
    const int ASZ = B_ * HEADS_ * P_;
    float* xout; float* attnout;
    if (out_size >= XSZ + ASZ)      { xout = (float*)d_out; attnout = (float*)d_out + XSZ; }
    else if (out_size >= ASZ)       { attnout = (float*)d_out; xout = xfall; }
    else                            { xout = (float*)d_out; attnout = (float*)0; }

    const int GEMM_SMEM = 4 * ATILE_H * 2;
    const int DWEXP_SMEM = (12 * HPX + 4 * HPX + 432 + 324 + 72 + 72 + HPX) * 4;
    cudaFuncSetAttribute(gemm_h,  cudaFuncAttributeMaxDynamicSharedMemorySize, GEMM_SMEM);
    cudaFuncSetAttribute(dwexp_k, cudaFuncAttributeMaxDynamicSharedMemorySize, DWEXP_SMEM);

    prep_k<<<WTOT / 256, 256>>>(qkv_w, (const float*)d_in[15],
                                (const float*)d_in[19], (const float*)d_in[21], wh, stats);
    ln_kernel<<<TOK_, 128>>>(x, ln1_g, ln1_b, hh);
    gemm_h<<<dim3(QKVN_ / 128, (TOK_ + 127) / 128), 256, GEMM_SMEM>>>(
        hh, wh, qkvb, TOK_, QKVN_, DIM_, 0, 0, 0, 0);
    attn_softmax_k<<<B_ * HEADS_, 256>>>(qkvb, attnb);

    gram_k<<<dim3(10, B_), 256>>>(attnb, stats);
    bn_fin1<<<1, 128>>>(stats, conv_exp_w, bn1_g, bn1_b, scb);

    dwexp_k<<<dim3(7, 9, B_), 256, DWEXP_SMEM>>>(attnb, conv_exp_w, scb, dw_w, adwb, stats + 96);
    bn_fin<<<1, 64>>>(stats + 96, bn2_g, bn2_b, scb + 36, HID_);

    conv_pro_k<<<CE_BLOCKS, 256>>>(adwb, attnb, conv_pro_w, scb + 36, aprob, stats + 180);
    bn3abn_fin<<<1, 32>>>(stats + 180, stats, bn3_g, bn3_b, abn_g, abn_b, coef);

    attn_av_k<<<dim3(B_ * HEADS_, 2), 256>>>(aprob, attnb, qkvb, coef, attnout, avh);

    gemm_h<<<dim3(DIM_ / 128, (TOK_ + 127) / 128), 256, GEMM_SMEM>>>(
        avh, wh + 442368, x1b, TOK_, DIM_, DIM_, 1, proj_b, x, 0);
    ln_kernel<<<TOK_, 128>>>(x1b, ln2_g, ln2_b, mh);
    gemm_h<<<dim3(MLPH_ / 128, (TOK_ + 127) / 128), 256, GEMM_SMEM>>>(
        mh, wh + 589824, (float*)mlph, TOK_, MLPH_, DIM_, 2, fc1_b, 0, 0);
    gemm_h<<<dim3(DIM_ / 128, (TOK_ + 127) / 128), 256, GEMM_SMEM>>>(
        mlph, wh + 1179648, xout, TOK_, DIM_, MLPH_, 3, fc2_b, x1b, scale_ch);
}

// round 16
// speedup vs baseline: 1.0436x; 1.0021x over previous
#include <cuda_runtime.h>
#include <cuda_fp16.h>
#include <math.h>
#include <stdint.h>

#define B_     32
#define NTOK   197
#define DIM_   384
#define HEADS_ 12
#define HD_    32
#define HID_   36
#define P_     38809        // 197*197
#define P4_    38812        // padded plane stride (16B-aligned quads)
#define QPP    9703         // quads per plane  (P4_/4)
#define TOK_   6304         // 32*197
#define QKVN_  1152
#define MLPH_  1536
#define CE_BLOCKS 592
#define WTOT   1769472

// dwexp tile: 32 wide x 24 tall, halo 34x26 = 884 px
#define TW     32
#define TH     24
#define HALOW  34
#define HALOH  26
#define HPX    884
#define HPX4   221

// ------------------------- scratch (static device globals) -------------------
__device__ __align__(128) __half g_hh  [TOK_ * DIM_];
__device__ __align__(128) float  g_qkv [TOK_ * QKVN_];
__device__ __align__(128) float  g_attn[(size_t)B_ * HEADS_ * P4_];
__device__ __align__(128) float  g_adw [(size_t)B_ * HID_   * P4_];
__device__ __align__(128) float  g_apro[(size_t)B_ * HEADS_ * P4_];
__device__ __align__(128) __half g_avh [TOK_ * DIM_];
__device__ __align__(128) float  g_x1  [TOK_ * DIM_];
__device__ __align__(128) __half g_mh  [TOK_ * DIM_];
__device__ __align__(128) __half g_mlph[TOK_ * MLPH_];
__device__ __align__(128) __half g_wh  [WTOT];
__device__ __align__(128) double g_stats[384];
__device__ __align__(128) float2 g_sc  [80];
__device__ __align__(128) float4 g_coef[16];
__device__ __align__(128) float  g_xfall[TOK_ * DIM_];

// ------------------------ prep: zero stats + weight convert ------------------
__global__ void prep_k(const float* __restrict__ qkvw, const float* __restrict__ projw,
                       const float* __restrict__ fc1w, const float* __restrict__ fc2w,
                       __half* __restrict__ wh, double* __restrict__ stats) {
    if (blockIdx.x == 0) {
        stats[threadIdx.x] = 0.0;
        if (threadIdx.x < 128) stats[256 + threadIdx.x] = 0.0;
    }
    int i = blockIdx.x * 256 + threadIdx.x;
    if (i >= WTOT) return;
    float v;
    if      (i < 442368)  v = qkvw[i];
    else if (i < 589824)  v = projw[i - 442368];
    else if (i < 1179648) v = fc1w[i - 589824];
    else                  v = fc2w[i - 1179648];
    wh[i] = __float2half(v);
}

// ------------------------------ LayerNorm (fp16 out) -------------------------
__global__ void ln_kernel(const float* __restrict__ x, const float* __restrict__ g,
                          const float* __restrict__ b, __half* __restrict__ out) {
    int t = blockIdx.x, tid = threadIdx.x;
    const float* xr = x + (size_t)t * DIM_;
    float v0 = 0.5f * xr[tid];
    float v1 = 0.5f * xr[tid + 128];
    float v2 = 0.5f * xr[tid + 256];
    float s  = v0 + v1 + v2;
    float s2 = v0 * v0 + v1 * v1 + v2 * v2;
    for (int o = 16; o; o >>= 1) {
        s  += __shfl_down_sync(0xffffffffu, s,  o);
        s2 += __shfl_down_sync(0xffffffffu, s2, o);
    }
    __shared__ float sh[4][2];
    __shared__ float mv[2];
    if ((tid & 31) == 0) { sh[tid >> 5][0] = s; sh[tid >> 5][1] = s2; }
    __syncthreads();
    if (tid == 0) {
        float S = sh[0][0] + sh[1][0] + sh[2][0] + sh[3][0];
        float S2 = sh[0][1] + sh[1][1] + sh[2][1] + sh[3][1];
        float mean = S / (float)DIM_;
        float var  = S2 / (float)DIM_ - mean * mean;
        mv[0] = mean; mv[1] = rsqrtf(var + 1e-5f);
    }
    __syncthreads();
    float mean = mv[0], inv = mv[1];
    __half* orow = out + (size_t)t * DIM_;
    orow[tid]       = __float2half((v0 - mean) * inv * g[tid]       + b[tid]);
    orow[tid + 128] = __float2half((v1 - mean) * inv * g[tid + 128] + b[tid + 128]);
    orow[tid + 256] = __float2half((v2 - mean) * inv * g[tid + 256] + b[tid + 256]);
}

// ------------------- fp16 tensor-core GEMM (m16n8k16, cp.async) --------------
#define HSTRIDE 72
#define ATILE_H (128 * HSTRIDE)

__global__ __launch_bounds__(256) void gemm_h(
        const __half* __restrict__ A, const __half* __restrict__ Bm,
        float* __restrict__ C, int M, int N, int K, int epi,
        const float* __restrict__ bias, const float* __restrict__ resid,
        const float* __restrict__ scale) {
    extern __shared__ __half shm[];
    __half* As = shm;
    __half* Bs = shm + 2 * ATILE_H;
    unsigned sa = (unsigned)__cvta_generic_to_shared(As);
    unsigned sbB = (unsigned)__cvta_generic_to_shared(Bs);
    int tid = threadIdx.x;
    int warp = tid >> 5, lane = tid & 31;
    int g = lane >> 2, tig = lane & 3;
    int wm = (warp & 1) * 64, wn = (warp >> 1) * 32;
    int m0 = blockIdx.y * 128, n0 = blockIdx.x * 128;

    float acc[4][4][4];
#pragma unroll
    for (int mi = 0; mi < 4; mi++)
#pragma unroll
        for (int nj = 0; nj < 4; nj++)
#pragma unroll
            for (int r = 0; r < 4; r++) acc[mi][nj][r] = 0.f;

    int nch = K >> 6;

#define HSTAGE(K0, BUF) do {                                                  \
        _Pragma("unroll")                                                     \
        for (int i = 0; i < 4; i++) {                                         \
            int idx = tid + i * 256;                                          \
            int r = idx >> 3, seg = idx & 7;                                  \
            int rowA = m0 + r; if (rowA >= M) rowA = M - 1;                   \
            asm volatile("cp.async.cg.shared.global [%0], [%1], 16;"          \
                :: "r"(sa + (unsigned)(((BUF) * ATILE_H + r * HSTRIDE + seg * 8) * 2)), \
                   "l"(A + (size_t)rowA * K + (K0) + seg * 8) : "memory");    \
            asm volatile("cp.async.cg.shared.global [%0], [%1], 16;"          \
                :: "r"(sbB + (unsigned)(((BUF) * ATILE_H + r * HSTRIDE + seg * 8) * 2)), \
                   "l"(Bm + (size_t)(n0 + r) * K + (K0) + seg * 8) : "memory"); \
        }                                                                     \
        asm volatile("cp.async.commit_group;" ::: "memory");                  \
    } while (0)

    HSTAGE(0, 0);
    HSTAGE(64, 1);
    for (int c = 0; c < nch; c++) {
        if (c + 1 < nch) asm volatile("cp.async.wait_group 1;" ::: "memory");
        else             asm volatile("cp.async.wait_group 0;" ::: "memory");
        __syncthreads();
        const unsigned* Au = (const unsigned*)(As + (c & 1) * ATILE_H);
        const unsigned* Bu = (const unsigned*)(Bs + (c & 1) * ATILE_H);
#pragma unroll
        for (int ks = 0; ks < 4; ks++) {
            unsigned a[4][4], bfr[4][2];
#pragma unroll
            for (int mi = 0; mi < 4; mi++) {
                int rr = wm + mi * 16 + g;
                int base = rr * 36 + ks * 8 + tig;
                a[mi][0] = Au[base];
                a[mi][1] = Au[base + 8 * 36];
                a[mi][2] = Au[base + 4];
                a[mi][3] = Au[base + 8 * 36 + 4];
            }
#pragma unroll
            for (int nj = 0; nj < 4; nj++) {
                int cc = wn + nj * 8 + g;
                int base = cc * 36 + ks * 8 + tig;
                bfr[nj][0] = Bu[base];
                bfr[nj][1] = Bu[base + 4];
            }
#pragma unroll
            for (int mi = 0; mi < 4; mi++)
#pragma unroll
                for (int nj = 0; nj < 4; nj++) {
                    asm volatile(
                        "mma.sync.aligned.m16n8k16.row.col.f32.f16.f16.f32 "
                        "{%0,%1,%2,%3},{%4,%5,%6,%7},{%8,%9},{%0,%1,%2,%3};"
                        : "+f"(acc[mi][nj][0]), "+f"(acc[mi][nj][1]),
                          "+f"(acc[mi][nj][2]), "+f"(acc[mi][nj][3])
                        : "r"(a[mi][0]), "r"(a[mi][1]), "r"(a[mi][2]), "r"(a[mi][3]),
                          "r"(bfr[nj][0]), "r"(bfr[nj][1]));
                }
        }
        __syncthreads();
        if (c + 2 < nch) HSTAGE((c + 2) << 6, c & 1);
    }

#pragma unroll
    for (int mi = 0; mi < 4; mi++) {
#pragma unroll
        for (int half = 0; half < 2; half++) {
            int row = m0 + wm + mi * 16 + g + half * 8;
            if (row >= M) continue;
#pragma unroll
            for (int nj = 0; nj < 4; nj++) {
                int col = n0 + wn + nj * 8 + 2 * tig;
                float v0 = acc[mi][nj][half * 2 + 0];
                float v1 = acc[mi][nj][half * 2 + 1];
                size_t o = (size_t)row * N + col;
                if (epi == 0) {
                    *(float2*)&C[o] = make_float2(v0, v1);
                } else if (epi == 1) {
                    *(float2*)&C[o] = make_float2(resid[o] + 2.f * (v0 + bias[col]),
                                                  resid[o + 1] + 2.f * (v1 + bias[col + 1]));
                } else if (epi == 2) {
                    float u0 = v0 + bias[col], u1 = v1 + bias[col + 1];
                    u0 = 0.5f * u0 * (1.f + erff(u0 * 0.70710678118654752f));
                    u1 = 0.5f * u1 * (1.f + erff(u1 * 0.70710678118654752f));
                    __half2 hv = __floats2half2_rn(u0, u1);
                    *(__half2*)&((__half*)C)[o] = hv;
                } else {
                    float u0 = (v0 + bias[col]) * scale[col];
                    float u1 = (v1 + bias[col + 1]) * scale[col + 1];
                    *(float2*)&C[o] = make_float2(resid[o] + 2.f * u0,
                                                  resid[o + 1] + 2.f * u1);
                }
            }
        }
    }
}

// ------------- attention logits + softmax; 4 rows/warp; fp32 out -------------
__global__ __launch_bounds__(256) void attn_softmax_k(const float* __restrict__ qkv,
        float* __restrict__ attn) {
    int bh = blockIdx.x, b = bh / HEADS_, h = bh - b * HEADS_;
    __shared__ float Ks[32 * 227];
    const float* base = qkv + (size_t)b * NTOK * QKVN_ + h * HD_;
    for (int i = threadIdx.x; i < NTOK * 32; i += 256) {
        int m = i >> 5, d = i & 31;
        Ks[d * 227 + m] = base[(size_t)m * QKVN_ + DIM_ + d];
    }
    __syncthreads();
    int lane = threadIdx.x & 31, w = threadIdx.x >> 5;
    float* arow = attn + (size_t)bh * P4_;
    for (int pass = 0; pass < 7; pass++) {
        int n0 = pass * 32 + w * 4;
        if (n0 >= NTOK) continue;
        float q0 = (n0 + 0 < NTOK) ? base[(size_t)(n0 + 0) * QKVN_ + lane] : 0.f;
        float q1 = (n0 + 1 < NTOK) ? base[(size_t)(n0 + 1) * QKVN_ + lane] : 0.f;
        float q2 = (n0 + 2 < NTOK) ? base[(size_t)(n0 + 2) * QKVN_ + lane] : 0.f;
        float q3 = (n0 + 3 < NTOK) ? base[(size_t)(n0 + 3) * QKVN_ + lane] : 0.f;
        float a[4][7];
#pragma unroll
        for (int r = 0; r < 4; r++)
#pragma unroll
            for (int j = 0; j < 7; j++) a[r][j] = 0.f;
#pragma unroll
        for (int d = 0; d < 32; d++) {
            float qv0 = __shfl_sync(0xffffffffu, q0, d);
            float qv1 = __shfl_sync(0xffffffffu, q1, d);
            float qv2 = __shfl_sync(0xffffffffu, q2, d);
            float qv3 = __shfl_sync(0xffffffffu, q3, d);
            const float* kc = &Ks[d * 227 + lane];
            float kj[7];
#pragma unroll
            for (int j = 0; j < 7; j++) kj[j] = kc[j * 32];
#pragma unroll
            for (int j = 0; j < 7; j++) {
                a[0][j] = fmaf(qv0, kj[j], a[0][j]);
                a[1][j] = fmaf(qv1, kj[j], a[1][j]);
                a[2][j] = fmaf(qv2, kj[j], a[2][j]);
                a[3][j] = fmaf(qv3, kj[j], a[3][j]);
            }
        }
#pragma unroll
        for (int r = 0; r < 4; r++) {
            int n = n0 + r;
            if (n >= NTOK) break;
            float* ar = a[r];
#pragma unroll
            for (int j = 0; j < 7; j++) ar[j] *= 0.17677669529663689f;
            if (lane >= 5) ar[6] = -INFINITY;
            float mx = ar[0];
#pragma unroll
            for (int j = 1; j < 7; j++) mx = fmaxf(mx, ar[j]);
            for (int o = 16; o; o >>= 1) mx = fmaxf(mx, __shfl_xor_sync(0xffffffffu, mx, o));
            float sum = 0.f;
#pragma unroll
            for (int j = 0; j < 7; j++) { ar[j] = __expf(ar[j] - mx); sum += ar[j]; }
            for (int o = 16; o; o >>= 1) sum += __shfl_xor_sync(0xffffffffu, sum, o);
            float inv = 1.f / sum;
#pragma unroll
            for (int j = 0; j < 7; j++) {
                int m = lane + 32 * j;
                if (m < NTOK) arow[(size_t)n * NTOK + m] = ar[j] * inv;
            }
        }
    }
}

// ---------------- Gram matrix of attn (12x12), float4 loads ------------------
__global__ __launch_bounds__(256) void gram_k(const float* __restrict__ attn,
                                              double* __restrict__ G) {
    int b = blockIdx.y;
    const float* ap = attn + (size_t)b * HEADS_ * P4_;
    float acc[78];
#pragma unroll
    for (int t = 0; t < 78; t++) acc[t] = 0.f;
    for (int q = blockIdx.x * 256 + threadIdx.x; q < QPP; q += gridDim.x * 256) {
        float4 a[12];
#pragma unroll
        for (int i = 0; i < 12; i++)
            a[i] = ((const float4*)(ap + (size_t)i * P4_))[q];
        int idx = 0;
#pragma unroll
        for (int i = 0; i < 12; i++)
#pragma unroll
            for (int j = 0; j <= i; j++) {
                acc[idx] = fmaf(a[i].x, a[j].x, acc[idx]);
                acc[idx] = fmaf(a[i].y, a[j].y, acc[idx]);
                acc[idx] = fmaf(a[i].z, a[j].z, acc[idx]);
                acc[idx] = fmaf(a[i].w, a[j].w, acc[idx]);
                idx++;
            }
    }
    __shared__ float red[8][78];
    int lane = threadIdx.x & 31, wp = threadIdx.x >> 5;
#pragma unroll
    for (int t = 0; t < 78; t++) {
        float v = acc[t];
        for (int o = 16; o; o >>= 1) v += __shfl_down_sync(0xffffffffu, v, o);
        if (lane == 0) red[wp][t] = v;
    }
    __syncthreads();
    if (threadIdx.x < 78) {
        float s = 0.f;
#pragma unroll
        for (int i = 0; i < 8; i++) s += red[i][threadIdx.x];
        atomicAdd(&G[threadIdx.x], (double)s);
    }
}

// bn1 from Gram
__global__ void bn_fin1(const double* __restrict__ G, const float* __restrict__ w,
                        const float* __restrict__ g, const float* __restrict__ b,
                        float2* __restrict__ sc) {
    __shared__ float Gs[78];
    if (threadIdx.x < 78) Gs[threadIdx.x] = (float)G[threadIdx.x];
    __syncthreads();
    int c = threadIdx.x;
    if (c >= HID_) return;
    float wr[12]; float rs = 0.f;
#pragma unroll
    for (int i = 0; i < 12; i++) { wr[i] = w[c * 12 + i]; rs += wr[i]; }
    float q = 0.f;
    int idx = 0;
#pragma unroll
    for (int i = 0; i < 12; i++) {
#pragma unroll
        for (int j = 0; j < i; j++) { q += 2.f * wr[i] * wr[j] * Gs[idx]; idx++; }
        q += wr[i] * wr[i] * Gs[idx]; idx++;
    }
    double mean = (double)rs / 197.0;
    double var  = (double)q / 1241888.0 - mean * mean;
    float s = (float)((double)g[c] / sqrt(var + 1e-5));
    sc[c] = make_float2(s, (float)((double)b[c] - mean * (double)s));
}

__global__ void bn_fin(const double* __restrict__ sums, const float* __restrict__ g,
                       const float* __restrict__ b, float2* __restrict__ sc, int C) {
    int c = threadIdx.x;
    if (c >= C) return;
    const double cnt = 1241888.0;
    double mean = sums[c] / cnt;
    double var  = sums[C + c] / cnt - mean * mean;
    float s = (float)((double)g[c] / sqrt(var + 1e-5));
    sc[c] = make_float2(s, (float)((double)b[c] - mean * (double)s));
}

// bn3 + abn analytic finalize
__global__ void bn3abn_fin(const double* __restrict__ S, const double* __restrict__ G,
                           const float* __restrict__ g3, const float* __restrict__ b3,
                           const float* __restrict__ gA, const float* __restrict__ bA,
                           float4* __restrict__ coef) {
    int h = threadIdx.x;
    if (h >= HEADS_) return;
    const double cnt = 1241888.0;
    double S1 = S[h], S2 = S[12 + h], X = S[24 + h];
    double mean3 = S1 / cnt, var3 = S2 / cnt - mean3 * mean3;
    double s3 = (double)g3[h] / sqrt(var3 + 1e-5);
    double sh3 = (double)b3[h] - mean3 * s3;
    double Sa0 = 6304.0;
    double Q = G[h * (h + 1) / 2 + h];
    double St  = s3 * S1 + cnt * sh3 + Sa0;
    double St2 = s3 * s3 * S2 + 2.0 * s3 * sh3 * S1 + cnt * sh3 * sh3
               + 2.0 * s3 * X + 2.0 * sh3 * Sa0 + Q;
    double meanA = St / cnt, varA = St2 / cnt - meanA * meanA;
    double sA = (double)gA[h] / sqrt(varA + 1e-5);
    double shA = (double)bA[h] - meanA * sA;
    coef[h] = make_float4((float)(sA * s3), (float)sA, (float)(sA * sh3 + shA), 0.f);
}

// -------- fused conv_expand + bn1 + relu6 + dw3x3 + bn2-stats (fp32) ---------
// 32x24 tile. Inputs loaded DIRECTLY from global into registers (no ain smem);
// expand from registers; dw sliding window. smem = et + weights only (~18KB).
__global__ __launch_bounds__(256, 3) void dwexp_k(const float* __restrict__ attn,
        const float* __restrict__ wexp, const float2* __restrict__ sc1,
        const float* __restrict__ dww, float* __restrict__ adw, double* __restrict__ sums) {
    extern __shared__ float sm[];
    float* et  = sm;                 // 4*HPX
    float* wE  = et + 4 * HPX;       // 432
    float* wD  = wE + 432;           // 324
    float* sc  = wD + 324;           // 72
    float* sacc = sc + 72;           // 72
    int tid = threadIdx.x;
    int b = blockIdx.z;
    int y0 = blockIdx.y * TH, x0 = blockIdx.x * TW;
    for (int i = tid; i < 432; i += 256) wE[i] = wexp[i];
    for (int i = tid; i < 324; i += 256) wD[i] = dww[i];
    if (tid < 36) { float2 s = sc1[tid]; sc[2 * tid] = s.x; sc[2 * tid + 1] = s.y; }
    if (tid < 72) sacc[tid] = 0.f;
    const float* ab = attn + (size_t)b * HEADS_ * P4_;
    // ---- load this thread's 4 halo pixels x 12 channels straight to regs ----
    bool haveq = (tid < HPX4);
    int myp = tid * 4;
    float4 vreg[12];
    float4 mreg = make_float4(0.f, 0.f, 0.f, 0.f);
#pragma unroll
    for (int i2 = 0; i2 < 12; i2++) vreg[i2] = make_float4(0.f, 0.f, 0.f, 0.f);
    if (haveq) {
#pragma unroll
        for (int k = 0; k < 4; k++) {
            int pp = myp + k;
            int ly = pp / HALOW, lx = pp - ly * HALOW;
            int gy = y0 + ly - 1, gx = x0 + lx - 1;
            bool in = (gy >= 0 && gy < NTOK && gx >= 0 && gx < NTOK);
            ((float*)&mreg)[k] = in ? 1.f : 0.f;
            if (in) {
                size_t off = (size_t)gy * NTOK + gx;
#pragma unroll
                for (int i2 = 0; i2 < 12; i2++)
                    ((float*)&vreg[i2])[k] = ab[(size_t)i2 * P4_ + off];
            }
        }
    }
    __syncthreads();   // (barrier to align weights smem fill with first use)
    int c4 = tid >> 6, t64 = tid & 63, tx = t64 & 31, ty0 = t64 >> 5;
    int lane = tid & 31;
    for (int cg = 0; cg < 9; cg++) {
        if (haveq) {
#pragma unroll
            for (int cc = 0; cc < 4; cc++) {
                int c = cg * 4 + cc;
                float4 s = make_float4(0.f, 0.f, 0.f, 0.f);
#pragma unroll
                for (int i2 = 0; i2 < 12; i2++) {
                    float wv = wE[c * 12 + i2];
                    s.x = fmaf(wv, vreg[i2].x, s.x);
                    s.y = fmaf(wv, vreg[i2].y, s.y);
                    s.z = fmaf(wv, vreg[i2].z, s.z);
                    s.w = fmaf(wv, vreg[i2].w, s.w);
                }
                float a = sc[2 * c], bb = sc[2 * c + 1];
                s.x = fminf(fmaxf(fmaf(a, s.x, bb), 0.f), 6.f) * mreg.x;
                s.y = fminf(fmaxf(fmaf(a, s.y, bb), 0.f), 6.f) * mreg.y;
                s.z = fminf(fmaxf(fmaf(a, s.z, bb), 0.f), 6.f) * mreg.z;
                s.w = fminf(fmaxf(fmaf(a, s.w, bb), 0.f), 6.f) * mreg.w;
                *(float4*)(et + cc * HPX + myp) = s;
            }
        }
        __syncthreads();
        int c = cg * 4 + c4;
        float w9[9];
#pragma unroll
        for (int k = 0; k < 9; k++) w9[k] = wD[c * 9 + k];
        const float* ep = et + c4 * HPX;
        float* op = adw + ((size_t)b * HID_ + c) * P4_;
        int ybase = ty0 * 12;
        int gx = x0 + tx;
        bool colok = (gx < NTOK);
        float ls = 0.f, ls2 = 0.f;
        float r1 = 0.f, r2 = 0.f;
#pragma unroll
        for (int yy = 0; yy < 14; yy++) {
            const float* rp = ep + (ybase + yy) * HALOW + tx;
            float v0 = rp[0], v1 = rp[1], v2 = rp[2];
            float c0 = fmaf(w9[0], v0, fmaf(w9[1], v1, w9[2] * v2));
            float c1 = fmaf(w9[3], v0, fmaf(w9[4], v1, w9[5] * v2));
            float c2 = fmaf(w9[6], v0, fmaf(w9[7], v1, w9[8] * v2));
            if (yy >= 2) {
                int gy = y0 + ybase + yy - 2;
                float out = r2 + c2;
                if (gy < NTOK && colok) {
                    op[gy * NTOK + gx] = out;
                    ls += out;
                    ls2 = fmaf(out, out, ls2);
                }
            }
            r2 = r1 + c1;
            r1 = c0;
        }
        for (int o = 16; o; o >>= 1) {
            ls  += __shfl_down_sync(0xffffffffu, ls,  o);
            ls2 += __shfl_down_sync(0xffffffffu, ls2, o);
        }
        if (lane == 0) { atomicAdd(&sacc[2 * c], ls); atomicAdd(&sacc[2 * c + 1], ls2); }
        __syncthreads();
    }
    if (tid < 36) {
        atomicAdd(&sums[tid],      (double)sacc[2 * tid]);
        atomicAdd(&sums[36 + tid], (double)sacc[2 * tid + 1]);
    }
}

// ---- conv_pro float4: 4 pixels/thread, bn2+relu6 on inputs + bn3 stats ------
__global__ __launch_bounds__(256) void conv_pro_k(const float* __restrict__ adw,
        const float* __restrict__ a0, const float* __restrict__ w,
        const float2* __restrict__ sc, float* __restrict__ apro, double* __restrict__ sums) {
    __shared__ float ws[HEADS_ * HID_];
    __shared__ float2 scs[HID_];
    int tid = threadIdx.x;
    for (int i = tid; i < HEADS_ * HID_; i += 256) ws[i] = w[i];
    if (tid < HID_) scs[tid] = sc[tid];
    __syncthreads();
    float s1[HEADS_], s2[HEADS_], sx[HEADS_];
#pragma unroll
    for (int o = 0; o < HEADS_; o++) { s1[o] = 0.f; s2[o] = 0.f; sx[o] = 0.f; }
    const int NQ = B_ * QPP;
    for (int q = blockIdx.x * 256 + tid; q < NQ; q += CE_BLOCKS * 256) {
        int b = q / QPP, qi = q - b * QPP;
        const float4* ip = (const float4*)(adw + (size_t)b * HID_ * P4_) + qi;
        float4 acc[HEADS_];
#pragma unroll
        for (int o = 0; o < HEADS_; o++) acc[o] = make_float4(0.f, 0.f, 0.f, 0.f);
#pragma unroll 6
        for (int i = 0; i < HID_; i++) {
            float4 v = ip[(size_t)i * QPP];
            float2 s = scs[i];
            v.x = fminf(fmaxf(fmaf(s.x, v.x, s.y), 0.f), 6.f);
            v.y = fminf(fmaxf(fmaf(s.x, v.y, s.y), 0.f), 6.f);
            v.z = fminf(fmaxf(fmaf(s.x, v.z, s.y), 0.f), 6.f);
            v.w = fminf(fmaxf(fmaf(s.x, v.w, s.y), 0.f), 6.f);
#pragma unroll
            for (int o = 0; o < HEADS_; o++) {
                float wv = ws[o * HID_ + i];
                acc[o].x = fmaf(wv, v.x, acc[o].x);
                acc[o].y = fmaf(wv, v.y, acc[o].y);
                acc[o].z = fmaf(wv, v.z, acc[o].z);
                acc[o].w = fmaf(wv, v.w, acc[o].w);
            }
        }
        int p = 4 * qi;
        float m1 = (p + 1 < P_) ? 1.f : 0.f;
        float m2 = (p + 2 < P_) ? 1.f : 0.f;
        float m3 = (p + 3 < P_) ? 1.f : 0.f;
        const float4* zp = (const float4*)(a0 + (size_t)b * HEADS_ * P4_) + qi;
        float4* op = (float4*)(apro + (size_t)b * HEADS_ * P4_) + qi;
#pragma unroll
        for (int o = 0; o < HEADS_; o++) {
            float4 a = acc[o];
            float4 z = zp[(size_t)o * QPP];
            op[(size_t)o * QPP] = a;
            float ay = a.y * m1, az = a.z * m2, aw = a.w * m3;
            s1[o] += a.x + ay + az + aw;
            s2[o] += a.x * a.x + ay * a.y + az * a.z + aw * a.w;
            sx[o] += a.x * z.x + ay * z.y + az * z.z + aw * z.w;
        }
    }
    int lane = tid & 31, wp = tid >> 5;
    __shared__ float red[8][36];
#pragma unroll
    for (int o = 0; o < HEADS_; o++) {
        float v = s1[o], v2 = s2[o], v3 = sx[o];
        for (int off = 16; off; off >>= 1) {
            v  += __shfl_down_sync(0xffffffffu, v,  off);
            v2 += __shfl_down_sync(0xffffffffu, v2, off);
            v3 += __shfl_down_sync(0xffffffffu, v3, off);
        }
        if (lane == 0) { red[wp][o] = v; red[wp][12 + o] = v2; red[wp][24 + o] = v3; }
    }
    __syncthreads();
    if (tid < 36) {
        float s = 0.f;
#pragma unroll
        for (int i = 0; i < 8; i++) s += red[i][tid];
        atomicAdd(&sums[tid], (double)s);
    }
}

// ---- attn_av: 4 rows/pass share V LDS; attn out fp32 + AV fp16 --------------
__global__ __launch_bounds__(256) void attn_av_k(const float* __restrict__ apro,
        const float* __restrict__ a0, const float* __restrict__ qkv,
        const float4* __restrict__ coef, float* __restrict__ attn_out,
        __half* __restrict__ av) {
    int bh = blockIdx.x, b = bh / HEADS_, h = bh - b * HEADS_;
    __shared__ float Vs[NTOK * 33];
    const float* vb = qkv + (size_t)b * NTOK * QKVN_ + 2 * DIM_ + h * HD_;
    int tid = threadIdx.x;
    for (int i = tid; i < NTOK * 32; i += 256) {
        int m = i >> 5, d = i & 31;
        Vs[m * 33 + d] = vb[(size_t)m * QKVN_ + d];
    }
    float4 cf = coef[h];
    const float* tp = apro + (size_t)bh * P4_;
    const float* zp = a0 + (size_t)bh * P4_;
    float* ao = attn_out ? attn_out + (size_t)bh * P_ : (float*)0;
    __syncthreads();
    int lane = tid & 31, w = tid >> 5;
    for (int r0 = 4 * (w + 8 * blockIdx.y); r0 < NTOK; r0 += 64) {
        int nv = NTOK - r0; if (nv > 4) nv = 4;
        float acc[4] = {0.f, 0.f, 0.f, 0.f};
#pragma unroll
        for (int mb = 0; mb < 192; mb += 32) {
            float tv[4];
#pragma unroll
            for (int r = 0; r < 4; r++) {
                if (r < nv) {
                    tv[r] = fmaf(cf.x, tp[(size_t)(r0 + r) * NTOK + mb + lane],
                                 fmaf(cf.y, zp[(size_t)(r0 + r) * NTOK + mb + lane], cf.z));
                    if (ao) ao[(size_t)(r0 + r) * NTOK + mb + lane] = tv[r];
                } else tv[r] = 0.f;
            }
#pragma unroll
            for (int j = 0; j < 32; j++) {
                float vv = Vs[(mb + j) * 33 + lane];
                acc[0] = fmaf(__shfl_sync(0xffffffffu, tv[0], j), vv, acc[0]);
                acc[1] = fmaf(__shfl_sync(0xffffffffu, tv[1], j), vv, acc[1]);
                acc[2] = fmaf(__shfl_sync(0xffffffffu, tv[2], j), vv, acc[2]);
                acc[3] = fmaf(__shfl_sync(0xffffffffu, tv[3], j), vv, acc[3]);
            }
        }
        {
            float tv[4];
#pragma unroll
            for (int r = 0; r < 4; r++) {
                tv[r] = 0.f;
                if (r < nv && lane < 5) {
                    tv[r] = fmaf(cf.x, tp[(size_t)(r0 + r) * NTOK + 192 + lane],
                                 fmaf(cf.y, zp[(size_t)(r0 + r) * NTOK + 192 + lane], cf.z));
                    if (ao) ao[(size_t)(r0 + r) * NTOK + 192 + lane] = tv[r];
                }
            }
#pragma unroll
            for (int j = 0; j < 5; j++) {
                float vv = Vs[(192 + j) * 33 + lane];
                acc[0] = fmaf(__shfl_sync(0xffffffffu, tv[0], j), vv, acc[0]);
                acc[1] = fmaf(__shfl_sync(0xffffffffu, tv[1], j), vv, acc[1]);
                acc[2] = fmaf(__shfl_sync(0xffffffffu, tv[2], j), vv, acc[2]);
                acc[3] = fmaf(__shfl_sync(0xffffffffu, tv[3], j), vv, acc[3]);
            }
        }
#pragma unroll
        for (int r = 0; r < 4; r++)
            if (r < nv)
                av[((size_t)(b * NTOK + r0 + r)) * DIM_ + h * HD_ + lane] = __float2half(acc[r]);
    }
}

// --------------------------------- launcher ----------------------------------
extern "C" void kernel_launch(void* const* d_in, const int* in_sizes, int n_in,
                              void* d_out, int out_size) {
    const float* x          = (const float*)d_in[0];
    const float* ln1_g      = (const float*)d_in[1];
    const float* ln1_b      = (const float*)d_in[2];
    const float* qkv_w      = (const float*)d_in[3];
    const float* conv_exp_w = (const float*)d_in[4];
    const float* bn1_g      = (const float*)d_in[5];
    const float* bn1_b      = (const float*)d_in[6];
    const float* dw_w       = (const float*)d_in[7];
    const float* bn2_g      = (const float*)d_in[8];
    const float* bn2_b      = (const float*)d_in[9];
    const float* conv_pro_w = (const float*)d_in[10];
    const float* bn3_g      = (const float*)d_in[11];
    const float* bn3_b      = (const float*)d_in[12];
    const float* abn_g      = (const float*)d_in[13];
    const float* abn_b      = (const float*)d_in[14];
    const float* proj_b     = (const float*)d_in[16];
    const float* ln2_g      = (const float*)d_in[17];
    const float* ln2_b      = (const float*)d_in[18];
    const float* fc1_b      = (const float*)d_in[20];
    const float* fc2_b      = (const float*)d_in[22];
    const float* scale_ch   = (const float*)d_in[23];

    void* p;
    cudaGetSymbolAddress(&p, g_hh);    __half* hh    = (__half*)p;
    cudaGetSymbolAddress(&p, g_qkv);   float*  qkvb  = (float*)p;
    cudaGetSymbolAddress(&p, g_attn);  float*  attnb = (float*)p;
    cudaGetSymbolAddress(&p, g_adw);   float*  adwb  = (float*)p;
    cudaGetSymbolAddress(&p, g_apro);  float*  aprob = (float*)p;
    cudaGetSymbolAddress(&p, g_avh);   __half* avh   = (__half*)p;
    cudaGetSymbolAddress(&p, g_x1);    float*  x1b   = (float*)p;
    cudaGetSymbolAddress(&p, g_mh);    __half* mh    = (__half*)p;
    cudaGetSymbolAddress(&p, g_mlph);  __half* mlph  = (__half*)p;
    cudaGetSymbolAddress(&p, g_wh);    __half* wh    = (__half*)p;
    cudaGetSymbolAddress(&p, g_stats); double* stats = (double*)p;
    cudaGetSymbolAddress(&p, g_sc);    float2* scb   = (float2*)p;
    cudaGetSymbolAddress(&p, g_coef);  float4* coef  = (float4*)p;
    cudaGetSymbolAddress(&p, g_xfall); float*  xfall = (float*)p;

    const int XSZ = TOK_ * DIM_;
    const int ASZ = B_ * HEADS_ * P_;
    float* xout; float* attnout;
    if (out_size >= XSZ + ASZ)      { xout = (float*)d_out; attnout = (float*)d_out + XSZ; }
    else if (out_size >= ASZ)       { attnout = (float*)d_out; xout = xfall; }
    else                            { xout = (float*)d_out; attnout = (float*)0; }

    const int GEMM_SMEM = 4 * ATILE_H * 2;
    const int DWEXP_SMEM = (4 * HPX + 432 + 324 + 72 + 72) * 4;   // 17744 B
    cudaFuncSetAttribute(gemm_h,  cudaFuncAttributeMaxDynamicSharedMemorySize, GEMM_SMEM);
    cudaFuncSetAttribute(dwexp_k, cudaFuncAttributeMaxDynamicSharedMemorySize, DWEXP_SMEM);

    prep_k<<<WTOT / 256, 256>>>(qkv_w, (const float*)d_in[15],
                                (const float*)d_in[19], (const float*)d_in[21], wh, stats);
    ln_kernel<<<TOK_, 128>>>(x, ln1_g, ln1_b, hh);
    gemm_h<<<dim3(QKVN_ / 128, (TOK_ + 127) / 128), 256, GEMM_SMEM>>>(
        hh, wh, qkvb, TOK_, QKVN_, DIM_, 0, 0, 0, 0);
    attn_softmax_k<<<B_ * HEADS_, 256>>>(qkvb, attnb);

    gram_k<<<dim3(10, B_), 256>>>(attnb, stats);
    bn_fin1<<<1, 128>>>(stats, conv_exp_w, bn1_g, bn1_b, scb);

    dwexp_k<<<dim3(7, 9, B_), 256, DWEXP_SMEM>>>(attnb, conv_exp_w, scb, dw_w, adwb, stats + 96);
    bn_fin<<<1, 64>>>(stats + 96, bn2_g, bn2_b, scb + 36, HID_);

    conv_pro_k<<<CE_BLOCKS, 256>>>(adwb, attnb, conv_pro_w, scb + 36, aprob, stats + 180);
    bn3abn_fin<<<1, 32>>>(stats + 180, stats, bn3_g, bn3_b, abn_g, abn_b, coef);

    attn_av_k<<<dim3(B_ * HEADS_, 2), 256>>>(aprob, attnb, qkvb, coef, attnout, avh);

    gemm_h<<<dim3(DIM_ / 128, (TOK_ + 127) / 128), 256, GEMM_SMEM>>>(
        avh, wh + 442368, x1b, TOK_, DIM_, DIM_, 1, proj_b, x, 0);
    ln_kernel<<<TOK_, 128>>>(x1b, ln2_g, ln2_b, mh);
    gemm_h<<<dim3(MLPH_ / 128, (TOK_ + 127) / 128), 256, GEMM_SMEM>>>(
        mh, wh + 589824, (float*)mlph, TOK_, MLPH_, DIM_, 2, fc1_b, 0, 0);
    gemm_h<<<dim3(DIM_ / 128, (TOK_ + 127) / 128), 256, GEMM_SMEM>>>(
        mlph, wh + 1179648, xout, TOK_, DIM_, MLPH_, 3, fc2_b, x1b, scale_ch);
}